// round 1
// baseline (speedup 1.0000x reference)
#include <cuda_runtime.h>
#include <cuda_bf16.h>
#include <mma.h>

using namespace nvcuda;

#define ROWS   8192     // BATCH*SEQLEN
#define BATCH  4
#define SEQ    2048
#define DM     1024     // d_model
#define DIN    2048     // d_inner
#define NH     32       // nheads
#define HD     64       // headdim
#define DS     16       // d_state
#define CONVD  2080     // conv dim
#define DPROJ  4160     // in-proj width
#define DPAD   4224     // padded to multiple of 128

// ---------------- scratch (static device globals; no runtime alloc) -------
__device__ float g_zx  [(size_t)ROWS * DPAD];   // in-proj output (padded)
__device__ float g_conv[(size_t)ROWS * CONVD];  // conv+silu output
__device__ float g_dt  [(size_t)ROWS * NH];     // softplus dt
__device__ float g_ys  [(size_t)ROWS * DIN];    // scan output
__device__ float g_yn  [(size_t)ROWS * DIN];    // gated+normed
__device__ float g_ob  [(size_t)ROWS * DM];     // out-proj raw product

// ---------------- generic tf32 wmma GEMM: C[M,N] = A[M,K] @ B[K,N] --------
// block tile 128x128, k-tile 32, 256 threads (8 warps -> 2x4, 64x32 each)
__global__ void __launch_bounds__(256, 2)
gemm_tf32(const float* __restrict__ A, const float* __restrict__ B,
          float* __restrict__ C, int M, int N, int K, int ldc)
{
    __shared__ float As[128 * 32];
    __shared__ float Bs[32 * 128];

    const int tid = threadIdx.x;
    const int m0  = blockIdx.y * 128;
    const int n0  = blockIdx.x * 128;
    const int wid = tid >> 5;
    const int wm  = wid & 1;    // 0..1 (64 rows each)
    const int wn  = wid >> 1;   // 0..3 (32 cols each)

    wmma::fragment<wmma::accumulator, 16, 16, 8, float> acc[4][2];
#pragma unroll
    for (int i = 0; i < 4; i++)
#pragma unroll
        for (int j = 0; j < 2; j++) wmma::fill_fragment(acc[i][j], 0.0f);

    const bool fullN = (n0 + 128 <= N);

    for (int k0 = 0; k0 < K; k0 += 32) {
        // ---- load A tile (128x32) as float4, convert to tf32 ----
#pragma unroll
        for (int it = 0; it < 4; ++it) {
            int idx = tid + it * 256;          // 0..1023
            int r   = idx >> 3;                // row 0..127
            int c4  = (idx & 7) << 2;          // col 0..28
            float4 v = *reinterpret_cast<const float4*>(
                A + (size_t)(m0 + r) * K + k0 + c4);
            float* d = As + r * 32 + c4;
            d[0] = wmma::__float_to_tf32(v.x);
            d[1] = wmma::__float_to_tf32(v.y);
            d[2] = wmma::__float_to_tf32(v.z);
            d[3] = wmma::__float_to_tf32(v.w);
        }
        // ---- load B tile (32x128) ----
        if (fullN) {
#pragma unroll
            for (int it = 0; it < 4; ++it) {
                int idx = tid + it * 256;
                int r   = idx >> 5;            // row 0..31
                int c4  = (idx & 31) << 2;     // col 0..124
                float4 v = *reinterpret_cast<const float4*>(
                    B + (size_t)(k0 + r) * N + n0 + c4);
                float* d = Bs + r * 128 + c4;
                d[0] = wmma::__float_to_tf32(v.x);
                d[1] = wmma::__float_to_tf32(v.y);
                d[2] = wmma::__float_to_tf32(v.z);
                d[3] = wmma::__float_to_tf32(v.w);
            }
        } else {
#pragma unroll
            for (int it = 0; it < 16; ++it) {
                int idx = tid + it * 256;      // 0..4095
                int r   = idx >> 7;
                int c   = idx & 127;
                float v = (n0 + c < N) ? B[(size_t)(k0 + r) * N + n0 + c] : 0.0f;
                Bs[r * 128 + c] = wmma::__float_to_tf32(v);
            }
        }
        __syncthreads();

#pragma unroll
        for (int kk = 0; kk < 32; kk += 8) {
            wmma::fragment<wmma::matrix_a, 16, 16, 8, wmma::precision::tf32, wmma::row_major> af[4];
            wmma::fragment<wmma::matrix_b, 16, 16, 8, wmma::precision::tf32, wmma::row_major> bf[2];
#pragma unroll
            for (int i = 0; i < 4; i++)
                wmma::load_matrix_sync(af[i], As + (wm * 64 + i * 16) * 32 + kk, 32);
#pragma unroll
            for (int j = 0; j < 2; j++)
                wmma::load_matrix_sync(bf[j], Bs + kk * 128 + wn * 32 + j * 16, 128);
#pragma unroll
            for (int i = 0; i < 4; i++)
#pragma unroll
                for (int j = 0; j < 2; j++)
                    wmma::mma_sync(acc[i][j], af[i], bf[j], acc[i][j]);
        }
        __syncthreads();
    }

#pragma unroll
    for (int i = 0; i < 4; i++)
#pragma unroll
        for (int j = 0; j < 2; j++) {
            int r = m0 + wm * 64 + i * 16;
            int c = n0 + wn * 32 + j * 16;
            wmma::store_matrix_sync(C + (size_t)r * ldc + c, acc[i][j], ldc,
                                    wmma::mem_row_major);
        }
}

// ---------------- dt = softplus(raw + dt_bias) ----------------------------
__global__ void dt_kernel(const float* __restrict__ zx,
                          const float* __restrict__ dt_bias,
                          float* __restrict__ dt)
{
    int idx = blockIdx.x * blockDim.x + threadIdx.x;
    if (idx >= ROWS * NH) return;
    int row = idx >> 5, h = idx & 31;
    float v = zx[(size_t)row * DPAD + DIN + CONVD + h] + dt_bias[h];
    dt[idx] = (v > 20.0f) ? v : log1pf(__expf(v));
}

// ---------------- causal depthwise conv1d + silu ---------------------------
__global__ void conv_kernel(const float* __restrict__ zx,
                            const float* __restrict__ cw,
                            const float* __restrict__ cb,
                            float* __restrict__ convout)
{
    int idx = blockIdx.x * blockDim.x + threadIdx.x;
    if (idx >= ROWS * CONVD) return;
    int row = idx / CONVD;
    int c   = idx - row * CONVD;
    int b   = row >> 11;
    int l   = row & 2047;
    float acc = cb[c];
#pragma unroll
    for (int k = 0; k < 4; k++) {
        int lt = l + k - 3;
        if (lt >= 0)
            acc += zx[(size_t)(b * SEQ + lt) * DPAD + DIN + c] * cw[c * 4 + k];
    }
    convout[idx] = acc / (1.0f + __expf(-acc));   // silu
}

// ---------------- sequential SSM scan: one block per (b,h) ----------------
#define CH 32
__global__ void __launch_bounds__(64, 4)
scan_kernel(const float* __restrict__ convout, const float* __restrict__ dt,
            const float* __restrict__ A_log, float* __restrict__ ys)
{
    int bh = blockIdx.x;
    int b  = bh >> 5, h = bh & 31;
    int p  = threadIdx.x;                 // 0..63 (headdim lane)
    float Aneg = -__expf(A_log[h]);

    float hst[DS];
#pragma unroll
    for (int n = 0; n < DS; n++) hst[n] = 0.0f;

    __shared__ __align__(16) float sB[CH][DS];
    __shared__ __align__(16) float sC[CH][DS];
    __shared__ float sdt[CH];

    const size_t rowbase = (size_t)b * SEQ;

    for (int t0 = 0; t0 < SEQ; t0 += CH) {
        // cooperative stage of B/C/dt
        for (int i = p; i < CH * DS; i += 64) {
            int tt = i >> 4, n = i & 15;
            size_t r = (rowbase + t0 + tt) * CONVD;
            sB[tt][n] = convout[r + DIN + n];
            sC[tt][n] = convout[r + DIN + DS + n];
        }
        for (int i = p; i < CH; i += 64)
            sdt[i] = dt[(rowbase + t0 + i) * NH + h];

        // prefetch xs for this lane (independent loads, MLP=CH)
        float rx[CH];
#pragma unroll
        for (int tt = 0; tt < CH; tt++)
            rx[tt] = convout[(rowbase + t0 + tt) * CONVD + h * HD + p];

        __syncthreads();

#pragma unroll
        for (int tt = 0; tt < CH; tt++) {
            float dtv = sdt[tt];
            float dAv = __expf(dtv * Aneg);
            float dtx = dtv * rx[tt];
            const float4* Bp = reinterpret_cast<const float4*>(sB[tt]);
            const float4* Cp = reinterpret_cast<const float4*>(sC[tt]);
            float yp0 = 0.f, yp1 = 0.f, yp2 = 0.f, yp3 = 0.f;
#pragma unroll
            for (int q = 0; q < 4; q++) {
                float4 Bv = Bp[q];
                float4 Cv = Cp[q];
                hst[q*4+0] = hst[q*4+0] * dAv + dtx * Bv.x; yp0 += hst[q*4+0] * Cv.x;
                hst[q*4+1] = hst[q*4+1] * dAv + dtx * Bv.y; yp1 += hst[q*4+1] * Cv.y;
                hst[q*4+2] = hst[q*4+2] * dAv + dtx * Bv.z; yp2 += hst[q*4+2] * Cv.z;
                hst[q*4+3] = hst[q*4+3] * dAv + dtx * Bv.w; yp3 += hst[q*4+3] * Cv.w;
            }
            ys[(rowbase + t0 + tt) * DIN + h * HD + p] = (yp0 + yp1) + (yp2 + yp3);
        }
        __syncthreads();
    }
}

// ---------------- y = (ys + D*xs) * silu(z); RMSNorm -----------------------
__global__ void __launch_bounds__(256)
post_kernel(const float* __restrict__ ys, const float* __restrict__ convout,
            const float* __restrict__ zx, const float* __restrict__ Dp,
            const float* __restrict__ nw, float* __restrict__ yn)
{
    int row = blockIdx.x;
    int tid = threadIdx.x;
    __shared__ float wsum[8];

    float vals[8];
    float ss = 0.0f;
#pragma unroll
    for (int i = 0; i < 8; i++) {
        int c = tid + i * 256;
        float xs = convout[(size_t)row * CONVD + c];
        float yv = ys[(size_t)row * DIN + c] + Dp[c >> 6] * xs;
        float z  = zx[(size_t)row * DPAD + c];
        float g  = z / (1.0f + __expf(-z));
        float v  = yv * g;
        vals[i] = v;
        ss += v * v;
    }
#pragma unroll
    for (int o = 16; o > 0; o >>= 1) ss += __shfl_xor_sync(0xffffffffu, ss, o);
    if ((tid & 31) == 0) wsum[tid >> 5] = ss;
    __syncthreads();
    float tot = 0.0f;
#pragma unroll
    for (int w = 0; w < 8; w++) tot += wsum[w];
    float scale = rsqrtf(tot * (1.0f / DIN) + 1e-5f);
#pragma unroll
    for (int i = 0; i < 8; i++) {
        int c = tid + i * 256;
        yn[(size_t)row * DIN + c] = vals[i] * scale * nw[c];
    }
}

// ---------------- out = x + ob * layer_scale --------------------------------
__global__ void final_kernel(const float* __restrict__ x,
                             const float* __restrict__ ob,
                             const float* __restrict__ ls,
                             float* __restrict__ out)
{
    int i4 = blockIdx.x * blockDim.x + threadIdx.x;
    if (i4 >= ROWS * DM / 4) return;
    int c4 = (i4 & (DM / 4 - 1)) << 2;
    float4 xv = reinterpret_cast<const float4*>(x)[i4];
    float4 ov = reinterpret_cast<const float4*>(ob)[i4];
    float4 lv = *reinterpret_cast<const float4*>(ls + c4);
    float4 r;
    r.x = xv.x + ov.x * lv.x;
    r.y = xv.y + ov.y * lv.y;
    r.z = xv.z + ov.z * lv.z;
    r.w = xv.w + ov.w * lv.w;
    reinterpret_cast<float4*>(out)[i4] = r;
}

// ---------------------------------------------------------------------------
extern "C" void kernel_launch(void* const* d_in, const int* in_sizes, int n_in,
                              void* d_out, int out_size)
{
    const float* x       = (const float*)d_in[0];
    const float* W_in    = (const float*)d_in[1];
    const float* conv_w  = (const float*)d_in[2];
    const float* conv_b  = (const float*)d_in[3];
    const float* dt_bias = (const float*)d_in[4];
    const float* A_log   = (const float*)d_in[5];
    const float* D_param = (const float*)d_in[6];
    const float* norm_w  = (const float*)d_in[7];
    const float* W_out   = (const float*)d_in[8];
    const float* lscale  = (const float*)d_in[9];
    float* out = (float*)d_out;

    float *zx, *conv, *dt, *ys, *yn, *ob;
    cudaGetSymbolAddress((void**)&zx,   g_zx);
    cudaGetSymbolAddress((void**)&conv, g_conv);
    cudaGetSymbolAddress((void**)&dt,   g_dt);
    cudaGetSymbolAddress((void**)&ys,   g_ys);
    cudaGetSymbolAddress((void**)&yn,   g_yn);
    cudaGetSymbolAddress((void**)&ob,   g_ob);

    // 1) in-proj GEMM: [8192,1024] @ [1024,4160] -> padded [8192,4224]
    gemm_tf32<<<dim3(33, 64), 256>>>(x, W_in, zx, ROWS, DPROJ, DM, DPAD);
    // 2) dt softplus
    dt_kernel<<<(ROWS * NH + 255) / 256, 256>>>(zx, dt_bias, dt);
    // 3) conv1d + silu
    conv_kernel<<<(ROWS * CONVD + 255) / 256, 256>>>(zx, conv_w, conv_b, conv);
    // 4) sequential SSM scan
    scan_kernel<<<BATCH * NH, 64>>>(conv, dt, A_log, ys);
    // 5) gate + RMSNorm
    post_kernel<<<ROWS, 256>>>(ys, conv, zx, D_param, norm_w, yn);
    // 6) out-proj GEMM: [8192,2048] @ [2048,1024]
    gemm_tf32<<<dim3(8, 64), 256>>>(yn, W_out, ob, ROWS, DM, DIN, DM);
    // 7) residual + layer scale
    final_kernel<<<(ROWS * DM / 4 + 255) / 256, 256>>>(x, ob, lscale, out);
}

// round 2
// speedup vs baseline: 3.8690x; 3.8690x over previous
#include <cuda_runtime.h>
#include <cuda_bf16.h>
#include <mma.h>

using namespace nvcuda;

#define ROWS   8192     // BATCH*SEQLEN
#define BATCH  4
#define SEQ    2048
#define DM     1024     // d_model
#define DIN    2048     // d_inner
#define NH     32       // nheads
#define HD     64       // headdim
#define DS     16       // d_state
#define CONVD  2080     // conv dim
#define DPROJ  4160     // in-proj width
#define DPAD   4224     // padded to multiple of 128
#define CL     128      // scan chunk length
#define NCH    16       // chunks per sequence

// ---------------- scratch (static device globals; no runtime alloc) -------
__device__ float          g_zx  [(size_t)ROWS * DPAD];    // in-proj output (padded)
__device__ float          g_conv[(size_t)ROWS * CONVD];   // conv+silu output
__device__ float          g_dt  [(size_t)ROWS * NH];      // softplus dt
__device__ float          g_dA  [(size_t)ROWS * NH];      // exp(dt*A)
__device__ float          g_ys  [(size_t)ROWS * DIN];     // scan output
__device__ float          g_ob  [(size_t)ROWS * DM];      // out-proj raw product
__device__ __nv_bfloat16  g_xb  [(size_t)ROWS * DM];      // x in bf16
__device__ __nv_bfloat16  g_wib [(size_t)DM * DPAD];      // W_in bf16, zero-padded
__device__ __nv_bfloat16  g_wob [(size_t)DIN * DM];       // W_out bf16
__device__ __nv_bfloat16  g_ynb [(size_t)ROWS * DIN];     // gated+normed, bf16
__device__ float          g_S   [(size_t)BATCH*NH*NCH*HD*DS]; // chunk end states
__device__ float          g_Hs  [(size_t)BATCH*NH*NCH*HD*DS]; // chunk start states
__device__ float          g_P   [(size_t)BATCH*NH*NCH];       // chunk decay products

// ---------------- helpers ---------------------------------------------------
__device__ __forceinline__ void cp16(void* smem, const void* g) {
    unsigned s = (unsigned)__cvta_generic_to_shared(smem);
    asm volatile("cp.async.ca.shared.global [%0], [%1], 16;\n" :: "r"(s), "l"(g));
}
#define CP_COMMIT() asm volatile("cp.async.commit_group;\n")
#define CP_WAIT0()  asm volatile("cp.async.wait_group 0;\n")

// ---------------- fp32 -> bf16 converters -----------------------------------
__global__ void cvt_plain(const float* __restrict__ src, __nv_bfloat16* __restrict__ dst, int n)
{
    int i = blockIdx.x * blockDim.x + threadIdx.x;
    if (i < n) dst[i] = __float2bfloat16(src[i]);
}
// W_in [DM][DPROJ] -> [DM][DPAD] with zero pad
__global__ void cvt_pad(const float* __restrict__ src, __nv_bfloat16* __restrict__ dst)
{
    int i = blockIdx.x * blockDim.x + threadIdx.x;
    if (i >= DM * DPAD) return;
    int r = i / DPAD, c = i - r * DPAD;
    dst[i] = __float2bfloat16(c < DPROJ ? src[(size_t)r * DPROJ + c] : 0.0f);
}

// ---------------- bf16 double-buffered GEMM: C[M,N]=A[M,K]@B[K,N] ----------
// tile 128x128, k-tile 32, 256 threads (8 warps -> 2x4, each 64x32)
__global__ void __launch_bounds__(256, 2)
gemm_bf16(const __nv_bfloat16* __restrict__ A, const __nv_bfloat16* __restrict__ B,
          float* __restrict__ C, int K, int lda, int ldb, int ldc)
{
    __shared__ __align__(16) __nv_bfloat16 As[2][128][40];
    __shared__ __align__(16) __nv_bfloat16 Bs[2][32][136];

    const int tid = threadIdx.x;
    const int m0  = blockIdx.y * 128;
    const int n0  = blockIdx.x * 128;
    const int wid = tid >> 5;
    const int wm  = wid & 1;
    const int wn  = wid >> 1;

    // per-thread load coords (2 chunks each for A and B)
    const int ar0 = tid >> 2,         ac0 = (tid & 3) << 3;
    const int ar1 = (tid + 256) >> 2, ac1 = ac0;
    const int br0 = tid >> 4,         bc0 = (tid & 15) << 3;
    const int br1 = (tid + 256) >> 4, bc1 = bc0;

    wmma::fragment<wmma::accumulator, 16, 16, 16, float> acc[4][2];
#pragma unroll
    for (int i = 0; i < 4; i++)
#pragma unroll
        for (int j = 0; j < 2; j++) wmma::fill_fragment(acc[i][j], 0.0f);

#define LOAD_TILE(buf, k0)                                                        \
    {                                                                             \
        cp16(&As[buf][ar0][ac0], A + (size_t)(m0 + ar0) * lda + (k0) + ac0);      \
        cp16(&As[buf][ar1][ac1], A + (size_t)(m0 + ar1) * lda + (k0) + ac1);      \
        cp16(&Bs[buf][br0][bc0], B + (size_t)((k0) + br0) * ldb + n0 + bc0);      \
        cp16(&Bs[buf][br1][bc1], B + (size_t)((k0) + br1) * ldb + n0 + bc1);      \
        CP_COMMIT();                                                              \
    }

    LOAD_TILE(0, 0);
    const int KT = K >> 5;
    for (int kt = 0; kt < KT; kt++) {
        CP_WAIT0();
        __syncthreads();
        if (kt + 1 < KT) LOAD_TILE((kt + 1) & 1, (kt + 1) << 5);
        const int buf = kt & 1;
#pragma unroll
        for (int kk = 0; kk < 32; kk += 16) {
            wmma::fragment<wmma::matrix_a, 16, 16, 16, __nv_bfloat16, wmma::row_major> af[4];
            wmma::fragment<wmma::matrix_b, 16, 16, 16, __nv_bfloat16, wmma::row_major> bf[2];
#pragma unroll
            for (int i = 0; i < 4; i++)
                wmma::load_matrix_sync(af[i], &As[buf][wm * 64 + i * 16][kk], 40);
#pragma unroll
            for (int j = 0; j < 2; j++)
                wmma::load_matrix_sync(bf[j], &Bs[buf][kk][wn * 32 + j * 16], 136);
#pragma unroll
            for (int i = 0; i < 4; i++)
#pragma unroll
                for (int j = 0; j < 2; j++)
                    wmma::mma_sync(acc[i][j], af[i], bf[j], acc[i][j]);
        }
    }
#undef LOAD_TILE

#pragma unroll
    for (int i = 0; i < 4; i++)
#pragma unroll
        for (int j = 0; j < 2; j++) {
            int r = m0 + wm * 64 + i * 16;
            int c = n0 + wn * 32 + j * 16;
            wmma::store_matrix_sync(C + (size_t)r * ldc + c, acc[i][j], ldc,
                                    wmma::mem_row_major);
        }
}

// ---------------- dt = softplus(raw + bias); dA = exp(dt * -exp(A_log)) ----
__global__ void dt_kernel(const float* __restrict__ zx,
                          const float* __restrict__ dt_bias,
                          const float* __restrict__ A_log,
                          float* __restrict__ dt, float* __restrict__ dA)
{
    int idx = blockIdx.x * blockDim.x + threadIdx.x;
    if (idx >= ROWS * NH) return;
    int row = idx >> 5, h = idx & 31;
    float v = zx[(size_t)row * DPAD + DIN + CONVD + h] + dt_bias[h];
    float d = (v > 20.0f) ? v : log1pf(__expf(v));
    dt[idx] = d;
    dA[idx] = __expf(d * (-__expf(A_log[h])));
}

// ---------------- causal depthwise conv1d + silu ---------------------------
__global__ void conv_kernel(const float* __restrict__ zx,
                            const float* __restrict__ cw,
                            const float* __restrict__ cb,
                            float* __restrict__ convout)
{
    int idx = blockIdx.x * blockDim.x + threadIdx.x;
    if (idx >= ROWS * CONVD) return;
    int row = idx / CONVD;
    int c   = idx - row * CONVD;
    int b   = row >> 11;
    int l   = row & 2047;
    float acc = cb[c];
#pragma unroll
    for (int k = 0; k < 4; k++) {
        int lt = l + k - 3;
        if (lt >= 0)
            acc += zx[(size_t)(b * SEQ + lt) * DPAD + DIN + c] * cw[c * 4 + k];
    }
    convout[idx] = acc / (1.0f + __expf(-acc));   // silu
}

// ---------------- scan phase A: per-chunk end state + decay product --------
__global__ void __launch_bounds__(64)
scanA(const float* __restrict__ convout, const float* __restrict__ dt,
      const float* __restrict__ dA, float* __restrict__ S, float* __restrict__ P)
{
    int blk = blockIdx.x;          // bh*NCH + c
    int bh  = blk >> 4, ch = blk & 15;
    int b   = bh >> 5,  h  = bh & 31;
    int p   = threadIdx.x;
    const size_t rowbase = (size_t)b * SEQ + ch * CL;

    float hst[DS];
#pragma unroll
    for (int n = 0; n < DS; n++) hst[n] = 0.0f;
    float pacc = 1.0f;

    __shared__ __align__(16) float sB[32][DS];
    __shared__ float sdt[32], sdA[32];

    for (int t0 = 0; t0 < CL; t0 += 32) {
        for (int i = p; i < 32 * DS; i += 64) {
            int tt = i >> 4, n = i & 15;
            sB[tt][n] = convout[(rowbase + t0 + tt) * CONVD + DIN + n];
        }
        for (int i = p; i < 32; i += 64) {
            sdt[i] = dt[(rowbase + t0 + i) * NH + h];
            sdA[i] = dA[(rowbase + t0 + i) * NH + h];
        }
        float rx[32];
#pragma unroll
        for (int tt = 0; tt < 32; tt++)
            rx[tt] = convout[(rowbase + t0 + tt) * CONVD + h * HD + p];
        __syncthreads();
#pragma unroll
        for (int tt = 0; tt < 32; tt++) {
            float dAv = sdA[tt];
            float dtx = sdt[tt] * rx[tt];
            pacc *= dAv;
            const float4* Bp = reinterpret_cast<const float4*>(sB[tt]);
#pragma unroll
            for (int q = 0; q < 4; q++) {
                float4 Bv = Bp[q];
                hst[q*4+0] = fmaf(hst[q*4+0], dAv, dtx * Bv.x);
                hst[q*4+1] = fmaf(hst[q*4+1], dAv, dtx * Bv.y);
                hst[q*4+2] = fmaf(hst[q*4+2], dAv, dtx * Bv.z);
                hst[q*4+3] = fmaf(hst[q*4+3], dAv, dtx * Bv.w);
            }
        }
        __syncthreads();
    }
    float4* Sp = reinterpret_cast<float4*>(S + (size_t)blk * (HD * DS) + p * DS);
#pragma unroll
    for (int q = 0; q < 4; q++)
        Sp[q] = make_float4(hst[q*4+0], hst[q*4+1], hst[q*4+2], hst[q*4+3]);
    if (p == 0) P[blk] = pacc;
}

// ---------------- scan phase B: inter-chunk recurrence ---------------------
__global__ void __launch_bounds__(256)
scanB(const float* __restrict__ S, const float* __restrict__ P,
      float* __restrict__ Hs)
{
    int bh  = blockIdx.x;
    int tid = threadIdx.x;                 // 4 states per thread
    float4 H = make_float4(0.f, 0.f, 0.f, 0.f);
    for (int c = 0; c < NCH; c++) {
        size_t off = ((size_t)bh * NCH + c) * (HD * DS) + tid * 4;
        *reinterpret_cast<float4*>(Hs + off) = H;
        float4 s = *reinterpret_cast<const float4*>(S + off);
        float pc = P[bh * NCH + c];
        H.x = H.x * pc + s.x;
        H.y = H.y * pc + s.y;
        H.z = H.z * pc + s.z;
        H.w = H.w * pc + s.w;
    }
}

// ---------------- scan phase C: chunk outputs from start state -------------
__global__ void __launch_bounds__(64)
scanC(const float* __restrict__ convout, const float* __restrict__ dt,
      const float* __restrict__ dA, const float* __restrict__ Hs,
      float* __restrict__ ys)
{
    int blk = blockIdx.x;
    int bh  = blk >> 4, ch = blk & 15;
    int b   = bh >> 5,  h  = bh & 31;
    int p   = threadIdx.x;
    const size_t rowbase = (size_t)b * SEQ + ch * CL;

    float hst[DS];
    {
        const float4* Hp = reinterpret_cast<const float4*>(
            Hs + (size_t)blk * (HD * DS) + p * DS);
#pragma unroll
        for (int q = 0; q < 4; q++) {
            float4 v = Hp[q];
            hst[q*4+0] = v.x; hst[q*4+1] = v.y; hst[q*4+2] = v.z; hst[q*4+3] = v.w;
        }
    }

    __shared__ __align__(16) float sB[32][DS];
    __shared__ __align__(16) float sC[32][DS];
    __shared__ float sdt[32], sdA[32];

    for (int t0 = 0; t0 < CL; t0 += 32) {
        for (int i = p; i < 32 * DS; i += 64) {
            int tt = i >> 4, n = i & 15;
            size_t r = (rowbase + t0 + tt) * CONVD;
            sB[tt][n] = convout[r + DIN + n];
            sC[tt][n] = convout[r + DIN + DS + n];
        }
        for (int i = p; i < 32; i += 64) {
            sdt[i] = dt[(rowbase + t0 + i) * NH + h];
            sdA[i] = dA[(rowbase + t0 + i) * NH + h];
        }
        float rx[32];
#pragma unroll
        for (int tt = 0; tt < 32; tt++)
            rx[tt] = convout[(rowbase + t0 + tt) * CONVD + h * HD + p];
        __syncthreads();
#pragma unroll
        for (int tt = 0; tt < 32; tt++) {
            float dAv = sdA[tt];
            float dtx = sdt[tt] * rx[tt];
            const float4* Bp = reinterpret_cast<const float4*>(sB[tt]);
            const float4* Cp = reinterpret_cast<const float4*>(sC[tt]);
            float yp0 = 0.f, yp1 = 0.f, yp2 = 0.f, yp3 = 0.f;
#pragma unroll
            for (int q = 0; q < 4; q++) {
                float4 Bv = Bp[q];
                float4 Cv = Cp[q];
                hst[q*4+0] = fmaf(hst[q*4+0], dAv, dtx * Bv.x); yp0 += hst[q*4+0] * Cv.x;
                hst[q*4+1] = fmaf(hst[q*4+1], dAv, dtx * Bv.y); yp1 += hst[q*4+1] * Cv.y;
                hst[q*4+2] = fmaf(hst[q*4+2], dAv, dtx * Bv.z); yp2 += hst[q*4+2] * Cv.z;
                hst[q*4+3] = fmaf(hst[q*4+3], dAv, dtx * Bv.w); yp3 += hst[q*4+3] * Cv.w;
            }
            ys[(rowbase + t0 + tt) * DIN + h * HD + p] = (yp0 + yp1) + (yp2 + yp3);
        }
        __syncthreads();
    }
}

// ---------------- y=(ys+D*xs)*silu(z); RMSNorm; emit bf16 -------------------
__global__ void __launch_bounds__(256)
post_kernel(const float* __restrict__ ys, const float* __restrict__ convout,
            const float* __restrict__ zx, const float* __restrict__ Dp,
            const float* __restrict__ nw, __nv_bfloat16* __restrict__ yn)
{
    int row = blockIdx.x;
    int tid = threadIdx.x;
    __shared__ float wsum[8];

    float vals[8];
    float ss = 0.0f;
#pragma unroll
    for (int i = 0; i < 8; i++) {
        int c = tid + i * 256;
        float xs = convout[(size_t)row * CONVD + c];
        float yv = ys[(size_t)row * DIN + c] + Dp[c >> 6] * xs;
        float z  = zx[(size_t)row * DPAD + c];
        float g  = z / (1.0f + __expf(-z));
        float v  = yv * g;
        vals[i] = v;
        ss += v * v;
    }
#pragma unroll
    for (int o = 16; o > 0; o >>= 1) ss += __shfl_xor_sync(0xffffffffu, ss, o);
    if ((tid & 31) == 0) wsum[tid >> 5] = ss;
    __syncthreads();
    float tot = 0.0f;
#pragma unroll
    for (int w = 0; w < 8; w++) tot += wsum[w];
    float scale = rsqrtf(tot * (1.0f / DIN) + 1e-5f);
#pragma unroll
    for (int i = 0; i < 8; i++) {
        int c = tid + i * 256;
        yn[(size_t)row * DIN + c] = __float2bfloat16(vals[i] * scale * nw[c]);
    }
}

// ---------------- out = x + ob * layer_scale --------------------------------
__global__ void final_kernel(const float* __restrict__ x,
                             const float* __restrict__ ob,
                             const float* __restrict__ ls,
                             float* __restrict__ out)
{
    int i4 = blockIdx.x * blockDim.x + threadIdx.x;
    if (i4 >= ROWS * DM / 4) return;
    int c4 = (i4 & (DM / 4 - 1)) << 2;
    float4 xv = reinterpret_cast<const float4*>(x)[i4];
    float4 ov = reinterpret_cast<const float4*>(ob)[i4];
    float4 lv = *reinterpret_cast<const float4*>(ls + c4);
    float4 r;
    r.x = xv.x + ov.x * lv.x;
    r.y = xv.y + ov.y * lv.y;
    r.z = xv.z + ov.z * lv.z;
    r.w = xv.w + ov.w * lv.w;
    reinterpret_cast<float4*>(out)[i4] = r;
}

// ---------------------------------------------------------------------------
extern "C" void kernel_launch(void* const* d_in, const int* in_sizes, int n_in,
                              void* d_out, int out_size)
{
    const float* x       = (const float*)d_in[0];
    const float* W_in    = (const float*)d_in[1];
    const float* conv_w  = (const float*)d_in[2];
    const float* conv_b  = (const float*)d_in[3];
    const float* dt_bias = (const float*)d_in[4];
    const float* A_log   = (const float*)d_in[5];
    const float* D_param = (const float*)d_in[6];
    const float* norm_w  = (const float*)d_in[7];
    const float* W_out   = (const float*)d_in[8];
    const float* lscale  = (const float*)d_in[9];
    float* out = (float*)d_out;

    float *zx, *conv, *dt, *dA, *ys, *ob, *S, *Hs, *P;
    __nv_bfloat16 *xb, *wib, *wob, *ynb;
    cudaGetSymbolAddress((void**)&zx,   g_zx);
    cudaGetSymbolAddress((void**)&conv, g_conv);
    cudaGetSymbolAddress((void**)&dt,   g_dt);
    cudaGetSymbolAddress((void**)&dA,   g_dA);
    cudaGetSymbolAddress((void**)&ys,   g_ys);
    cudaGetSymbolAddress((void**)&ob,   g_ob);
    cudaGetSymbolAddress((void**)&S,    g_S);
    cudaGetSymbolAddress((void**)&Hs,   g_Hs);
    cudaGetSymbolAddress((void**)&P,    g_P);
    cudaGetSymbolAddress((void**)&xb,   g_xb);
    cudaGetSymbolAddress((void**)&wib,  g_wib);
    cudaGetSymbolAddress((void**)&wob,  g_wob);
    cudaGetSymbolAddress((void**)&ynb,  g_ynb);

    // 0) converters
    cvt_plain<<<(ROWS * DM + 255) / 256, 256>>>(x, xb, ROWS * DM);
    cvt_pad  <<<(DM * DPAD + 255) / 256, 256>>>(W_in, wib);
    cvt_plain<<<(DIN * DM + 255) / 256, 256>>>(W_out, wob, DIN * DM);

    // 1) in-proj GEMM: [8192,1024] @ [1024,4224] -> [8192,4224]
    gemm_bf16<<<dim3(DPAD / 128, ROWS / 128), 256>>>(xb, wib, zx, DM, DM, DPAD, DPAD);
    // 2) dt softplus + dA
    dt_kernel<<<(ROWS * NH + 255) / 256, 256>>>(zx, dt_bias, A_log, dt, dA);
    // 3) conv1d + silu
    conv_kernel<<<(ROWS * CONVD + 255) / 256, 256>>>(zx, conv_w, conv_b, conv);
    // 4) chunked SSM scan
    scanA<<<BATCH * NH * NCH, 64>>>(conv, dt, dA, S, P);
    scanB<<<BATCH * NH, 256>>>(S, P, Hs);
    scanC<<<BATCH * NH * NCH, 64>>>(conv, dt, dA, Hs, ys);
    // 5) gate + RMSNorm -> bf16
    post_kernel<<<ROWS, 256>>>(ys, conv, zx, D_param, norm_w, ynb);
    // 6) out-proj GEMM: [8192,2048] @ [2048,1024]
    gemm_bf16<<<dim3(DM / 128, ROWS / 128), 256>>>(ynb, wob, ob, DIN, DIN, DM, DM);
    // 7) residual + layer scale
    final_kernel<<<(ROWS * DM / 4 + 255) / 256, 256>>>(x, ob, lscale, out);
}

// round 6
// speedup vs baseline: 3.8692x; 1.0000x over previous
#include <cuda_runtime.h>
#include <cuda_bf16.h>
#include <mma.h>
#include <cstdint>

using namespace nvcuda;

#define ROWS   8192     // BATCH*SEQLEN
#define BATCH  4
#define SEQ    2048
#define DM     1024     // d_model
#define DIN    2048     // d_inner
#define NH     32       // nheads
#define HD     64       // headdim
#define DS     16       // d_state
#define CONVD  2080     // conv dim
#define DPROJ  4160     // in-proj width
#define DPAD   4352     // padded to multiple of 256
#define CL     128      // scan chunk length
#define NCH    16       // chunks per sequence

// ---------------- scratch (static device globals; no runtime alloc) -------
__device__ float          g_zx  [(size_t)ROWS * DPAD];
__device__ float          g_conv[(size_t)ROWS * CONVD];
__device__ float          g_dt  [(size_t)ROWS * NH];
__device__ float          g_dA  [(size_t)ROWS * NH];
__device__ float          g_ys  [(size_t)ROWS * DIN];
__device__ float          g_ob  [(size_t)ROWS * DM];
__device__ __nv_bfloat16  g_xb  [(size_t)ROWS * DM];
__device__ __nv_bfloat16  g_wib [(size_t)DM * DPAD];   // W_in bf16 [k][n], zero-padded
__device__ __nv_bfloat16  g_wob [(size_t)DIN * DM];    // W_out bf16 [k][n]
__device__ __nv_bfloat16  g_ynb [(size_t)ROWS * DIN];
__device__ float          g_S   [(size_t)BATCH*NH*NCH*HD*DS];
__device__ float          g_Hs  [(size_t)BATCH*NH*NCH*HD*DS];
__device__ float          g_P   [(size_t)BATCH*NH*NCH];

// ================= helpers =================================================
__device__ __forceinline__ void cp16(void* smem, const void* g) {
    unsigned s = (unsigned)__cvta_generic_to_shared(smem);
    asm volatile("cp.async.ca.shared.global [%0], [%1], 16;\n" :: "r"(s), "l"(g));
}
#define CP_COMMIT() asm volatile("cp.async.commit_group;\n" ::: "memory")
#define CP_WAIT0()  asm volatile("cp.async.wait_group 0;\n" ::: "memory")

// ================= bf16 double-buffered GEMM: C[M,N]=A[M,K]@B[K,N] =========
// A row-major [m][k], B row-major [k][n]. CTA 128x256, warp 64x64 (2m x 4n),
// k-tile 32, 2-stage cp.async double buffer (R2-proven control flow).
#define AROW  40                         // A smem row stride (halves)
#define BROW  264                        // B smem row stride (halves)
#define A_H   (128 * AROW)               // 5120 halves
#define B_H   (32 * BROW)                // 8448 halves
#define STG_H (A_H + B_H)                // 13568 halves
#define SMEM_GEMM (2 * STG_H * 2)        // 54272 bytes

__global__ void __launch_bounds__(256, 1)
gemm_bf16(const __nv_bfloat16* __restrict__ A, const __nv_bfloat16* __restrict__ B,
          float* __restrict__ C, int K, int lda, int ldb, int ldc)
{
    extern __shared__ __nv_bfloat16 sm[];
    const int tid = threadIdx.x;
    const int wid = tid >> 5;
    const int wm  = wid >> 2;        // 0..1
    const int wn  = wid & 3;         // 0..3
    const int m0  = blockIdx.y << 7;
    const int n0  = blockIdx.x << 8;

    wmma::fragment<wmma::accumulator, 16, 16, 16, float> acc[4][4];
#pragma unroll
    for (int i = 0; i < 4; i++)
#pragma unroll
        for (int j = 0; j < 4; j++) wmma::fill_fragment(acc[i][j], 0.0f);

#define LOAD_TILE(buf, k0)                                                       \
    {                                                                            \
        __nv_bfloat16* sA = sm + (buf) * STG_H;                                  \
        __nv_bfloat16* sB = sA + A_H;                                            \
        _Pragma("unroll")                                                        \
        for (int it = 0; it < 2; ++it) {                                         \
            int idx = tid + it * 256;                                            \
            int r   = idx >> 2;                                                  \
            int c   = (idx & 3) << 3;                                            \
            cp16(sA + r * AROW + c, A + (size_t)(m0 + r) * lda + (k0) + c);      \
        }                                                                        \
        _Pragma("unroll")                                                        \
        for (int it = 0; it < 4; ++it) {                                         \
            int idx = tid + it * 256;                                            \
            int r   = idx >> 5;                                                  \
            int c   = (idx & 31) << 3;                                           \
            cp16(sB + r * BROW + c, B + (size_t)((k0) + r) * ldb + n0 + c);      \
        }                                                                        \
        CP_COMMIT();                                                             \
    }

    LOAD_TILE(0, 0);
    const int KT = K >> 5;
    for (int kt = 0; kt < KT; kt++) {
        CP_WAIT0();
        __syncthreads();
        if (kt + 1 < KT) LOAD_TILE((kt + 1) & 1, (kt + 1) << 5);
        const int buf = kt & 1;
        const __nv_bfloat16* sA = sm + buf * STG_H + (wm * 64) * AROW;
        const __nv_bfloat16* sB = sm + buf * STG_H + A_H + wn * 64;
#pragma unroll
        for (int kk = 0; kk < 32; kk += 16) {
            wmma::fragment<wmma::matrix_a, 16, 16, 16, __nv_bfloat16,
                           wmma::row_major> af[4];
#pragma unroll
            for (int i = 0; i < 4; i++)
                wmma::load_matrix_sync(af[i], sA + (i * 16) * AROW + kk, AROW);
#pragma unroll
            for (int j = 0; j < 4; j++) {
                wmma::fragment<wmma::matrix_b, 16, 16, 16, __nv_bfloat16,
                               wmma::row_major> bf;
                wmma::load_matrix_sync(bf, sB + kk * BROW + j * 16, BROW);
#pragma unroll
                for (int i = 0; i < 4; i++)
                    wmma::mma_sync(acc[i][j], af[i], bf, acc[i][j]);
            }
        }
        __syncthreads();
    }
#undef LOAD_TILE

#pragma unroll
    for (int i = 0; i < 4; i++)
#pragma unroll
        for (int j = 0; j < 4; j++) {
            int r = m0 + wm * 64 + i * 16;
            int c = n0 + wn * 64 + j * 16;
            wmma::store_matrix_sync(C + (size_t)r * ldc + c, acc[i][j], ldc,
                                    wmma::mem_row_major);
        }
}

// ================= converters ==============================================
__global__ void cvt_plain(const float* __restrict__ src, __nv_bfloat16* __restrict__ dst, int n)
{
    int i = blockIdx.x * blockDim.x + threadIdx.x;
    if (i < n) dst[i] = __float2bfloat16(src[i]);
}
// W_in [DM][DPROJ] -> [DM][DPAD] with zero pad (row-major, R2-proven)
__global__ void cvt_pad(const float* __restrict__ src, __nv_bfloat16* __restrict__ dst)
{
    int i = blockIdx.x * blockDim.x + threadIdx.x;
    if (i >= DM * DPAD) return;
    int r = i / DPAD, c = i - r * DPAD;
    dst[i] = __float2bfloat16(c < DPROJ ? src[(size_t)r * DPROJ + c] : 0.0f);
}

// ================= dt / dA ==================================================
__global__ void dt_kernel(const float* __restrict__ zx,
                          const float* __restrict__ dt_bias,
                          const float* __restrict__ A_log,
                          float* __restrict__ dt, float* __restrict__ dA)
{
    int idx = blockIdx.x * blockDim.x + threadIdx.x;
    if (idx >= ROWS * NH) return;
    int row = idx >> 5, h = idx & 31;
    float v = zx[(size_t)row * DPAD + DIN + CONVD + h] + dt_bias[h];
    float d = (v > 20.0f) ? v : log1pf(__expf(v));
    dt[idx] = d;
    dA[idx] = __expf(d * (-__expf(A_log[h])));
}

// ================= causal depthwise conv1d + silu (sliding window) =========
// one thread: 4 consecutive timesteps of one channel
__global__ void conv_kernel(const float* __restrict__ zx,
                            const float* __restrict__ cw,
                            const float* __restrict__ cb,
                            float* __restrict__ convout)
{
    int idx = blockIdx.x * blockDim.x + threadIdx.x;
    if (idx >= (ROWS / 4) * CONVD) return;
    int rowq = idx / CONVD;
    int c    = idx - rowq * CONVD;
    int b    = rowq >> 9;                 // 512 row-quads per batch
    int lq   = (rowq & 511) << 2;         // starting timestep

    float w0 = cw[c * 4 + 0], w1 = cw[c * 4 + 1];
    float w2 = cw[c * 4 + 2], w3 = cw[c * 4 + 3];
    float bias = cb[c];

    float v[7];
#pragma unroll
    for (int j = 0; j < 7; j++) {
        int lt = lq + j - 3;
        v[j] = (lt >= 0) ? zx[(size_t)(b * SEQ + lt) * DPAD + DIN + c] : 0.0f;
    }
#pragma unroll
    for (int t = 0; t < 4; t++) {
        float acc = bias + v[t] * w0 + v[t + 1] * w1 + v[t + 2] * w2 + v[t + 3] * w3;
        convout[(size_t)(b * SEQ + lq + t) * CONVD + c] = acc / (1.0f + __expf(-acc));
    }
}

// ================= chunked SSM scan ========================================
__global__ void __launch_bounds__(64)
scanA(const float* __restrict__ convout, const float* __restrict__ dt,
      const float* __restrict__ dA, float* __restrict__ S, float* __restrict__ P)
{
    int blk = blockIdx.x;
    int bh  = blk >> 4, ch = blk & 15;
    int b   = bh >> 5,  h  = bh & 31;
    int p   = threadIdx.x;
    const size_t rowbase = (size_t)b * SEQ + ch * CL;

    float hst[DS];
#pragma unroll
    for (int n = 0; n < DS; n++) hst[n] = 0.0f;
    float pacc = 1.0f;

    __shared__ __align__(16) float sB[32][DS];
    __shared__ float sdt[32], sdA[32];

    for (int t0 = 0; t0 < CL; t0 += 32) {
        for (int i = p; i < 32 * DS; i += 64) {
            int tt = i >> 4, n = i & 15;
            sB[tt][n] = convout[(rowbase + t0 + tt) * CONVD + DIN + n];
        }
        for (int i = p; i < 32; i += 64) {
            sdt[i] = dt[(rowbase + t0 + i) * NH + h];
            sdA[i] = dA[(rowbase + t0 + i) * NH + h];
        }
        float rx[32];
#pragma unroll
        for (int tt = 0; tt < 32; tt++)
            rx[tt] = convout[(rowbase + t0 + tt) * CONVD + h * HD + p];
        __syncthreads();
#pragma unroll
        for (int tt = 0; tt < 32; tt++) {
            float dAv = sdA[tt];
            float dtx = sdt[tt] * rx[tt];
            pacc *= dAv;
            const float4* Bp = reinterpret_cast<const float4*>(sB[tt]);
#pragma unroll
            for (int q = 0; q < 4; q++) {
                float4 Bv = Bp[q];
                hst[q*4+0] = fmaf(hst[q*4+0], dAv, dtx * Bv.x);
                hst[q*4+1] = fmaf(hst[q*4+1], dAv, dtx * Bv.y);
                hst[q*4+2] = fmaf(hst[q*4+2], dAv, dtx * Bv.z);
                hst[q*4+3] = fmaf(hst[q*4+3], dAv, dtx * Bv.w);
            }
        }
        __syncthreads();
    }
    float4* Sp = reinterpret_cast<float4*>(S + (size_t)blk * (HD * DS) + p * DS);
#pragma unroll
    for (int q = 0; q < 4; q++)
        Sp[q] = make_float4(hst[q*4+0], hst[q*4+1], hst[q*4+2], hst[q*4+3]);
    if (p == 0) P[blk] = pacc;
}

__global__ void __launch_bounds__(256)
scanB(const float* __restrict__ S, const float* __restrict__ P,
      float* __restrict__ Hs)
{
    int bh  = blockIdx.x;
    int tid = threadIdx.x;
    float4 H = make_float4(0.f, 0.f, 0.f, 0.f);
    for (int c = 0; c < NCH; c++) {
        size_t off = ((size_t)bh * NCH + c) * (HD * DS) + tid * 4;
        *reinterpret_cast<float4*>(Hs + off) = H;
        float4 sv = *reinterpret_cast<const float4*>(S + off);
        float pc = P[bh * NCH + c];
        H.x = H.x * pc + sv.x;
        H.y = H.y * pc + sv.y;
        H.z = H.z * pc + sv.z;
        H.w = H.w * pc + sv.w;
    }
}

__global__ void __launch_bounds__(64)
scanC(const float* __restrict__ convout, const float* __restrict__ dt,
      const float* __restrict__ dA, const float* __restrict__ Hs,
      float* __restrict__ ys)
{
    int blk = blockIdx.x;
    int bh  = blk >> 4, ch = blk & 15;
    int b   = bh >> 5,  h  = bh & 31;
    int p   = threadIdx.x;
    const size_t rowbase = (size_t)b * SEQ + ch * CL;

    float hst[DS];
    {
        const float4* Hp = reinterpret_cast<const float4*>(
            Hs + (size_t)blk * (HD * DS) + p * DS);
#pragma unroll
        for (int q = 0; q < 4; q++) {
            float4 v = Hp[q];
            hst[q*4+0] = v.x; hst[q*4+1] = v.y; hst[q*4+2] = v.z; hst[q*4+3] = v.w;
        }
    }

    __shared__ __align__(16) float sB[32][DS];
    __shared__ __align__(16) float sC[32][DS];
    __shared__ float sdt[32], sdA[32];

    for (int t0 = 0; t0 < CL; t0 += 32) {
        for (int i = p; i < 32 * DS; i += 64) {
            int tt = i >> 4, n = i & 15;
            size_t r = (rowbase + t0 + tt) * CONVD;
            sB[tt][n] = convout[r + DIN + n];
            sC[tt][n] = convout[r + DIN + DS + n];
        }
        for (int i = p; i < 32; i += 64) {
            sdt[i] = dt[(rowbase + t0 + i) * NH + h];
            sdA[i] = dA[(rowbase + t0 + i) * NH + h];
        }
        float rx[32];
#pragma unroll
        for (int tt = 0; tt < 32; tt++)
            rx[tt] = convout[(rowbase + t0 + tt) * CONVD + h * HD + p];
        __syncthreads();
#pragma unroll
        for (int tt = 0; tt < 32; tt++) {
            float dAv = sdA[tt];
            float dtx = sdt[tt] * rx[tt];
            const float4* Bp = reinterpret_cast<const float4*>(sB[tt]);
            const float4* Cp = reinterpret_cast<const float4*>(sC[tt]);
            float yp0 = 0.f, yp1 = 0.f, yp2 = 0.f, yp3 = 0.f;
#pragma unroll
            for (int q = 0; q < 4; q++) {
                float4 Bv = Bp[q];
                float4 Cv = Cp[q];
                hst[q*4+0] = fmaf(hst[q*4+0], dAv, dtx * Bv.x); yp0 += hst[q*4+0] * Cv.x;
                hst[q*4+1] = fmaf(hst[q*4+1], dAv, dtx * Bv.y); yp1 += hst[q*4+1] * Cv.y;
                hst[q*4+2] = fmaf(hst[q*4+2], dAv, dtx * Bv.z); yp2 += hst[q*4+2] * Cv.z;
                hst[q*4+3] = fmaf(hst[q*4+3], dAv, dtx * Bv.w); yp3 += hst[q*4+3] * Cv.w;
            }
            ys[(rowbase + t0 + tt) * DIN + h * HD + p] = (yp0 + yp1) + (yp2 + yp3);
        }
        __syncthreads();
    }
}

// ================= gate + RMSNorm -> bf16 ==================================
__global__ void __launch_bounds__(256)
post_kernel(const float* __restrict__ ys, const float* __restrict__ convout,
            const float* __restrict__ zx, const float* __restrict__ Dp,
            const float* __restrict__ nw, __nv_bfloat16* __restrict__ yn)
{
    int row = blockIdx.x;
    int tid = threadIdx.x;
    __shared__ float wsum[8];

    float vals[8];
    float ss = 0.0f;
#pragma unroll
    for (int i = 0; i < 8; i++) {
        int c = tid + i * 256;
        float xs = convout[(size_t)row * CONVD + c];
        float yv = ys[(size_t)row * DIN + c] + Dp[c >> 6] * xs;
        float z  = zx[(size_t)row * DPAD + c];
        float g  = z / (1.0f + __expf(-z));
        float v  = yv * g;
        vals[i] = v;
        ss += v * v;
    }
#pragma unroll
    for (int o = 16; o > 0; o >>= 1) ss += __shfl_xor_sync(0xffffffffu, ss, o);
    if ((tid & 31) == 0) wsum[tid >> 5] = ss;
    __syncthreads();
    float tot = 0.0f;
#pragma unroll
    for (int w = 0; w < 8; w++) tot += wsum[w];
    float scale = rsqrtf(tot * (1.0f / DIN) + 1e-5f);
#pragma unroll
    for (int i = 0; i < 8; i++) {
        int c = tid + i * 256;
        yn[(size_t)row * DIN + c] = __float2bfloat16(vals[i] * scale * nw[c]);
    }
}

// ================= out = x + ob * layer_scale ===============================
__global__ void final_kernel(const float* __restrict__ x,
                             const float* __restrict__ ob,
                             const float* __restrict__ ls,
                             float* __restrict__ out)
{
    int i4 = blockIdx.x * blockDim.x + threadIdx.x;
    if (i4 >= ROWS * DM / 4) return;
    int c4 = (i4 & (DM / 4 - 1)) << 2;
    float4 xv = reinterpret_cast<const float4*>(x)[i4];
    float4 ov = reinterpret_cast<const float4*>(ob)[i4];
    float4 lv = *reinterpret_cast<const float4*>(ls + c4);
    float4 r;
    r.x = xv.x + ov.x * lv.x;
    r.y = xv.y + ov.y * lv.y;
    r.z = xv.z + ov.z * lv.z;
    r.w = xv.w + ov.w * lv.w;
    reinterpret_cast<float4*>(out)[i4] = r;
}

// ===========================================================================
extern "C" void kernel_launch(void* const* d_in, const int* in_sizes, int n_in,
                              void* d_out, int out_size)
{
    const float* x       = (const float*)d_in[0];
    const float* W_in    = (const float*)d_in[1];
    const float* conv_w  = (const float*)d_in[2];
    const float* conv_b  = (const float*)d_in[3];
    const float* dt_bias = (const float*)d_in[4];
    const float* A_log   = (const float*)d_in[5];
    const float* D_param = (const float*)d_in[6];
    const float* norm_w  = (const float*)d_in[7];
    const float* W_out   = (const float*)d_in[8];
    const float* lscale  = (const float*)d_in[9];
    float* out = (float*)d_out;

    float *zx, *conv, *dt, *dA, *ys, *ob, *S, *Hs, *P;
    __nv_bfloat16 *xb, *wib, *wob, *ynb;
    cudaGetSymbolAddress((void**)&zx,   g_zx);
    cudaGetSymbolAddress((void**)&conv, g_conv);
    cudaGetSymbolAddress((void**)&dt,   g_dt);
    cudaGetSymbolAddress((void**)&dA,   g_dA);
    cudaGetSymbolAddress((void**)&ys,   g_ys);
    cudaGetSymbolAddress((void**)&ob,   g_ob);
    cudaGetSymbolAddress((void**)&S,    g_S);
    cudaGetSymbolAddress((void**)&Hs,   g_Hs);
    cudaGetSymbolAddress((void**)&P,    g_P);
    cudaGetSymbolAddress((void**)&xb,   g_xb);
    cudaGetSymbolAddress((void**)&wib,  g_wib);
    cudaGetSymbolAddress((void**)&wob,  g_wob);
    cudaGetSymbolAddress((void**)&ynb,  g_ynb);

    cudaFuncSetAttribute(gemm_bf16, cudaFuncAttributeMaxDynamicSharedMemorySize,
                         SMEM_GEMM);

    // 0) converters
    cvt_plain<<<(ROWS * DM + 255) / 256, 256>>>(x, xb, ROWS * DM);
    cvt_pad  <<<(DM * DPAD + 255) / 256, 256>>>(W_in, wib);
    cvt_plain<<<(DIN * DM + 255) / 256, 256>>>(W_out, wob, DIN * DM);

    // 1) in-proj GEMM: [8192,1024] @ [1024,4352] -> zx [8192,4352]
    gemm_bf16<<<dim3(DPAD / 256, ROWS / 128), 256, SMEM_GEMM>>>(
        xb, wib, zx, DM, DM, DPAD, DPAD);
    // 2) dt softplus + dA
    dt_kernel<<<(ROWS * NH + 255) / 256, 256>>>(zx, dt_bias, A_log, dt, dA);
    // 3) conv1d + silu (sliding window, 4 steps/thread)
    conv_kernel<<<((ROWS / 4) * CONVD + 255) / 256, 256>>>(zx, conv_w, conv_b, conv);
    // 4) chunked SSM scan
    scanA<<<BATCH * NH * NCH, 64>>>(conv, dt, dA, S, P);
    scanB<<<BATCH * NH, 256>>>(S, P, Hs);
    scanC<<<BATCH * NH * NCH, 64>>>(conv, dt, dA, Hs, ys);
    // 5) gate + RMSNorm -> bf16
    post_kernel<<<ROWS, 256>>>(ys, conv, zx, D_param, norm_w, ynb);
    // 6) out-proj GEMM: [8192,2048] @ W_out[2048,1024] -> ob
    gemm_bf16<<<dim3(DM / 256, ROWS / 128), 256, SMEM_GEMM>>>(
        ynb, wob, ob, DIN, DIN, DM, DM);
    // 7) residual + layer scale
    final_kernel<<<(ROWS * DM / 4 + 255) / 256, 256>>>(x, ob, lscale, out);
}

// round 8
// speedup vs baseline: 4.0881x; 1.0566x over previous
#include <cuda_runtime.h>
#include <cuda_bf16.h>
#include <mma.h>
#include <cstdint>

using namespace nvcuda;

#define ROWS   8192     // BATCH*SEQLEN
#define BATCH  4
#define SEQ    2048
#define DM     1024     // d_model
#define DIN    2048     // d_inner
#define NH     32       // nheads
#define HD     64       // headdim
#define DS     16       // d_state
#define CONVD  2080     // conv dim
#define DPROJ  4160     // in-proj width
#define DPAD   4352     // padded (mult of 128)
#define CL     128      // scan chunk length
#define NCH    16       // chunks per sequence

// ---------------- scratch (static device globals; no runtime alloc) -------
__device__ float          g_zx  [(size_t)ROWS * DPAD];
__device__ float          g_conv[(size_t)ROWS * CONVD];
__device__ float          g_dt  [(size_t)ROWS * NH];
__device__ float          g_dA  [(size_t)ROWS * NH];
__device__ float          g_ys  [(size_t)ROWS * DIN];
__device__ __nv_bfloat16  g_xb  [(size_t)ROWS * DM];
__device__ __nv_bfloat16  g_wib [(size_t)DM * DPAD];   // W_in bf16 [k][n], zero-padded
__device__ __nv_bfloat16  g_wob [(size_t)DIN * DM];    // W_out bf16 [k][n]
__device__ __nv_bfloat16  g_ynb [(size_t)ROWS * DIN];
__device__ float          g_S   [(size_t)BATCH*NH*NCH*HD*DS];
__device__ float          g_Hs  [(size_t)BATCH*NH*NCH*HD*DS];
__device__ float          g_P   [(size_t)BATCH*NH*NCH];

// ================= helpers =================================================
__device__ __forceinline__ void cp16(void* smem, const void* g) {
    unsigned s = (unsigned)__cvta_generic_to_shared(smem);
    asm volatile("cp.async.ca.shared.global [%0], [%1], 16;\n" :: "r"(s), "l"(g));
}
#define CP_COMMIT() asm volatile("cp.async.commit_group;\n" ::: "memory")
#define CP_WAIT0()  asm volatile("cp.async.wait_group 0;\n" ::: "memory")

// ================= bf16 double-buffered GEMM: C[M,N]=A[M,K]@B[K,N] =========
// A row-major [m][k], B row-major [k][n]. CTA 128x128, 128 threads (4 warps),
// warp tile 64x64 (2m x 2n). k-tile 32, 2-stage double buffer.
// Optional fused epilogue: out = xres + acc*ls (per-column ls).
#define AROW  40                         // A smem row stride (halves)
#define BROW  136                        // B smem row stride (halves)
#define A_H   (128 * AROW)               // 5120 halves
#define B_H   (32 * BROW)                // 4352 halves
#define STG_H (A_H + B_H)                // 9472 halves
#define SMEM_GEMM (2 * STG_H * 2)        // 37888 bytes

__global__ void __launch_bounds__(128, 2)
gemm_bf16(const __nv_bfloat16* __restrict__ A, const __nv_bfloat16* __restrict__ B,
          float* __restrict__ C, int K, int lda, int ldb, int ldc,
          const float* __restrict__ xres, const float* __restrict__ ls)
{
    extern __shared__ __nv_bfloat16 sm[];
    const int tid = threadIdx.x;
    const int wid = tid >> 5;
    const int lid = tid & 31;
    const int wm  = wid >> 1;        // 0..1
    const int wn  = wid & 1;         // 0..1
    const int m0  = blockIdx.y << 7;
    const int n0  = blockIdx.x << 7;

    wmma::fragment<wmma::accumulator, 16, 16, 16, float> acc[4][4];
#pragma unroll
    for (int i = 0; i < 4; i++)
#pragma unroll
        for (int j = 0; j < 4; j++) wmma::fill_fragment(acc[i][j], 0.0f);

    // Each cp16 moves 16 BYTES = 8 halves.
    // A tile: 128 rows x 32 halves = 512 segs; 128 thr x 4 iters.
    // B tile: 32 rows x 128 halves = 512 segs; 128 thr x 4 iters.
#define LOAD_TILE(buf, k0)                                                       \
    {                                                                            \
        __nv_bfloat16* sA = sm + (buf) * STG_H;                                  \
        __nv_bfloat16* sB = sA + A_H;                                            \
        _Pragma("unroll")                                                        \
        for (int it = 0; it < 4; ++it) {                                         \
            int idx = tid + it * 128;                                            \
            int r   = idx >> 2;                                                  \
            int c   = (idx & 3) << 3;                                            \
            cp16(sA + r * AROW + c, A + (size_t)(m0 + r) * lda + (k0) + c);      \
        }                                                                        \
        _Pragma("unroll")                                                        \
        for (int it = 0; it < 4; ++it) {                                         \
            int idx = tid + it * 128;                                            \
            int r   = idx >> 4;                                                  \
            int c   = (idx & 15) << 3;                                           \
            cp16(sB + r * BROW + c, B + (size_t)((k0) + r) * ldb + n0 + c);      \
        }                                                                        \
        CP_COMMIT();                                                             \
    }

    LOAD_TILE(0, 0);
    const int KT = K >> 5;
    for (int kt = 0; kt < KT; kt++) {
        CP_WAIT0();
        __syncthreads();
        if (kt + 1 < KT) LOAD_TILE((kt + 1) & 1, (kt + 1) << 5);
        const int buf = kt & 1;
        const __nv_bfloat16* sA = sm + buf * STG_H + (wm * 64) * AROW;
        const __nv_bfloat16* sB = sm + buf * STG_H + A_H + wn * 64;
#pragma unroll
        for (int kk = 0; kk < 32; kk += 16) {
            wmma::fragment<wmma::matrix_a, 16, 16, 16, __nv_bfloat16,
                           wmma::row_major> af[4];
#pragma unroll
            for (int i = 0; i < 4; i++)
                wmma::load_matrix_sync(af[i], sA + (i * 16) * AROW + kk, AROW);
#pragma unroll
            for (int j = 0; j < 4; j++) {
                wmma::fragment<wmma::matrix_b, 16, 16, 16, __nv_bfloat16,
                               wmma::row_major> bf;
                wmma::load_matrix_sync(bf, sB + kk * BROW + j * 16, BROW);
#pragma unroll
                for (int i = 0; i < 4; i++)
                    wmma::mma_sync(acc[i][j], af[i], bf, acc[i][j]);
            }
        }
        __syncthreads();
    }
#undef LOAD_TILE

    if (xres == nullptr) {
#pragma unroll
        for (int i = 0; i < 4; i++)
#pragma unroll
            for (int j = 0; j < 4; j++) {
                int r = m0 + wm * 64 + i * 16;
                int c = n0 + wn * 64 + j * 16;
                wmma::store_matrix_sync(C + (size_t)r * ldc + c, acc[i][j], ldc,
                                        wmma::mem_row_major);
            }
    } else {
        // fused: out = xres + acc * ls, via per-warp smem round-trip
        __syncthreads();
        float* scr = reinterpret_cast<float*>(sm) + wid * 256;
        const int rr = lid >> 1;            // 0..15
        const int cc = (lid & 1) << 3;      // 0 or 8
#pragma unroll
        for (int i = 0; i < 4; i++)
#pragma unroll
            for (int j = 0; j < 4; j++) {
                wmma::store_matrix_sync(scr, acc[i][j], 16, wmma::mem_row_major);
                __syncwarp();
                int r = m0 + wm * 64 + i * 16 + rr;
                int c = n0 + wn * 64 + j * 16 + cc;
                const float* xs = xres + (size_t)r * ldc + c;
                const float* sv = scr + rr * 16 + cc;
                float4 o0, o1;
                o0.x = xs[0] + sv[0] * ls[c + 0];
                o0.y = xs[1] + sv[1] * ls[c + 1];
                o0.z = xs[2] + sv[2] * ls[c + 2];
                o0.w = xs[3] + sv[3] * ls[c + 3];
                o1.x = xs[4] + sv[4] * ls[c + 4];
                o1.y = xs[5] + sv[5] * ls[c + 5];
                o1.z = xs[6] + sv[6] * ls[c + 6];
                o1.w = xs[7] + sv[7] * ls[c + 7];
                float* dst = C + (size_t)r * ldc + c;
                *reinterpret_cast<float4*>(dst)     = o0;
                *reinterpret_cast<float4*>(dst + 4) = o1;
                __syncwarp();
            }
    }
}

// ================= converters ==============================================
__global__ void cvt_plain(const float* __restrict__ src, __nv_bfloat16* __restrict__ dst, int n)
{
    int i = blockIdx.x * blockDim.x + threadIdx.x;
    if (i < n) dst[i] = __float2bfloat16(src[i]);
}
// W_in [DM][DPROJ] -> [DM][DPAD] with zero pad
__global__ void cvt_pad(const float* __restrict__ src, __nv_bfloat16* __restrict__ dst)
{
    int i = blockIdx.x * blockDim.x + threadIdx.x;
    if (i >= DM * DPAD) return;
    int r = i / DPAD, c = i - r * DPAD;
    dst[i] = __float2bfloat16(c < DPROJ ? src[(size_t)r * DPROJ + c] : 0.0f);
}

// ================= dt / dA ==================================================
__global__ void dt_kernel(const float* __restrict__ zx,
                          const float* __restrict__ dt_bias,
                          const float* __restrict__ A_log,
                          float* __restrict__ dt, float* __restrict__ dA)
{
    int idx = blockIdx.x * blockDim.x + threadIdx.x;
    if (idx >= ROWS * NH) return;
    int row = idx >> 5, h = idx & 31;
    float v = zx[(size_t)row * DPAD + DIN + CONVD + h] + dt_bias[h];
    float d = (v > 20.0f) ? v : log1pf(__expf(v));
    dt[idx] = d;
    dA[idx] = __expf(d * (-__expf(A_log[h])));
}

// ================= causal depthwise conv1d + silu (sliding window) =========
__global__ void conv_kernel(const float* __restrict__ zx,
                            const float* __restrict__ cw,
                            const float* __restrict__ cb,
                            float* __restrict__ convout)
{
    int idx = blockIdx.x * blockDim.x + threadIdx.x;
    if (idx >= (ROWS / 4) * CONVD) return;
    int rowq = idx / CONVD;
    int c    = idx - rowq * CONVD;
    int b    = rowq >> 9;
    int lq   = (rowq & 511) << 2;

    float w0 = cw[c * 4 + 0], w1 = cw[c * 4 + 1];
    float w2 = cw[c * 4 + 2], w3 = cw[c * 4 + 3];
    float bias = cb[c];

    float v[7];
#pragma unroll
    for (int j = 0; j < 7; j++) {
        int lt = lq + j - 3;
        v[j] = (lt >= 0) ? zx[(size_t)(b * SEQ + lt) * DPAD + DIN + c] : 0.0f;
    }
#pragma unroll
    for (int t = 0; t < 4; t++) {
        float acc = bias + v[t] * w0 + v[t + 1] * w1 + v[t + 2] * w2 + v[t + 3] * w3;
        convout[(size_t)(b * SEQ + lq + t) * CONVD + c] = acc / (1.0f + __expf(-acc));
    }
}

// ================= chunked SSM scan ========================================
__global__ void __launch_bounds__(64)
scanA(const float* __restrict__ convout, const float* __restrict__ dt,
      const float* __restrict__ dA, float* __restrict__ S, float* __restrict__ P)
{
    int blk = blockIdx.x;
    int bh  = blk >> 4, ch = blk & 15;
    int b   = bh >> 5,  h  = bh & 31;
    int p   = threadIdx.x;
    const size_t rowbase = (size_t)b * SEQ + ch * CL;

    float hst[DS];
#pragma unroll
    for (int n = 0; n < DS; n++) hst[n] = 0.0f;
    float pacc = 1.0f;

    __shared__ __align__(16) float sB[32][DS];
    __shared__ float sdt[32], sdA[32];

    for (int t0 = 0; t0 < CL; t0 += 32) {
        for (int i = p; i < 32 * DS; i += 64) {
            int tt = i >> 4, n = i & 15;
            sB[tt][n] = convout[(rowbase + t0 + tt) * CONVD + DIN + n];
        }
        for (int i = p; i < 32; i += 64) {
            sdt[i] = dt[(rowbase + t0 + i) * NH + h];
            sdA[i] = dA[(rowbase + t0 + i) * NH + h];
        }
        float rx[32];
#pragma unroll
        for (int tt = 0; tt < 32; tt++)
            rx[tt] = convout[(rowbase + t0 + tt) * CONVD + h * HD + p];
        __syncthreads();
#pragma unroll
        for (int tt = 0; tt < 32; tt++) {
            float dAv = sdA[tt];
            float dtx = sdt[tt] * rx[tt];
            pacc *= dAv;
            const float4* Bp = reinterpret_cast<const float4*>(sB[tt]);
#pragma unroll
            for (int q = 0; q < 4; q++) {
                float4 Bv = Bp[q];
                hst[q*4+0] = fmaf(hst[q*4+0], dAv, dtx * Bv.x);
                hst[q*4+1] = fmaf(hst[q*4+1], dAv, dtx * Bv.y);
                hst[q*4+2] = fmaf(hst[q*4+2], dAv, dtx * Bv.z);
                hst[q*4+3] = fmaf(hst[q*4+3], dAv, dtx * Bv.w);
            }
        }
        __syncthreads();
    }
    float4* Sp = reinterpret_cast<float4*>(S + (size_t)blk * (HD * DS) + p * DS);
#pragma unroll
    for (int q = 0; q < 4; q++)
        Sp[q] = make_float4(hst[q*4+0], hst[q*4+1], hst[q*4+2], hst[q*4+3]);
    if (p == 0) P[blk] = pacc;
}

__global__ void __launch_bounds__(256)
scanB(const float* __restrict__ S, const float* __restrict__ P,
      float* __restrict__ Hs)
{
    int bh  = blockIdx.x;
    int tid = threadIdx.x;
    float4 H = make_float4(0.f, 0.f, 0.f, 0.f);
    for (int c = 0; c < NCH; c++) {
        size_t off = ((size_t)bh * NCH + c) * (HD * DS) + tid * 4;
        *reinterpret_cast<float4*>(Hs + off) = H;
        float4 sv = *reinterpret_cast<const float4*>(S + off);
        float pc = P[bh * NCH + c];
        H.x = H.x * pc + sv.x;
        H.y = H.y * pc + sv.y;
        H.z = H.z * pc + sv.z;
        H.w = H.w * pc + sv.w;
    }
}

__global__ void __launch_bounds__(64)
scanC(const float* __restrict__ convout, const float* __restrict__ dt,
      const float* __restrict__ dA, const float* __restrict__ Hs,
      float* __restrict__ ys)
{
    int blk = blockIdx.x;
    int bh  = blk >> 4, ch = blk & 15;
    int b   = bh >> 5,  h  = bh & 31;
    int p   = threadIdx.x;
    const size_t rowbase = (size_t)b * SEQ + ch * CL;

    float hst[DS];
    {
        const float4* Hp = reinterpret_cast<const float4*>(
            Hs + (size_t)blk * (HD * DS) + p * DS);
#pragma unroll
        for (int q = 0; q < 4; q++) {
            float4 v = Hp[q];
            hst[q*4+0] = v.x; hst[q*4+1] = v.y; hst[q*4+2] = v.z; hst[q*4+3] = v.w;
        }
    }

    __shared__ __align__(16) float sB[32][DS];
    __shared__ __align__(16) float sC[32][DS];
    __shared__ float sdt[32], sdA[32];

    for (int t0 = 0; t0 < CL; t0 += 32) {
        for (int i = p; i < 32 * DS; i += 64) {
            int tt = i >> 4, n = i & 15;
            size_t r = (rowbase + t0 + tt) * CONVD;
            sB[tt][n] = convout[r + DIN + n];
            sC[tt][n] = convout[r + DIN + DS + n];
        }
        for (int i = p; i < 32; i += 64) {
            sdt[i] = dt[(rowbase + t0 + i) * NH + h];
            sdA[i] = dA[(rowbase + t0 + i) * NH + h];
        }
        float rx[32];
#pragma unroll
        for (int tt = 0; tt < 32; tt++)
            rx[tt] = convout[(rowbase + t0 + tt) * CONVD + h * HD + p];
        __syncthreads();
#pragma unroll
        for (int tt = 0; tt < 32; tt++) {
            float dAv = sdA[tt];
            float dtx = sdt[tt] * rx[tt];
            const float4* Bp = reinterpret_cast<const float4*>(sB[tt]);
            const float4* Cp = reinterpret_cast<const float4*>(sC[tt]);
            float yp0 = 0.f, yp1 = 0.f, yp2 = 0.f, yp3 = 0.f;
#pragma unroll
            for (int q = 0; q < 4; q++) {
                float4 Bv = Bp[q];
                float4 Cv = Cp[q];
                hst[q*4+0] = fmaf(hst[q*4+0], dAv, dtx * Bv.x); yp0 += hst[q*4+0] * Cv.x;
                hst[q*4+1] = fmaf(hst[q*4+1], dAv, dtx * Bv.y); yp1 += hst[q*4+1] * Cv.y;
                hst[q*4+2] = fmaf(hst[q*4+2], dAv, dtx * Bv.z); yp2 += hst[q*4+2] * Cv.z;
                hst[q*4+3] = fmaf(hst[q*4+3], dAv, dtx * Bv.w); yp3 += hst[q*4+3] * Cv.w;
            }
            ys[(rowbase + t0 + tt) * DIN + h * HD + p] = (yp0 + yp1) + (yp2 + yp3);
        }
        __syncthreads();
    }
}

// ================= gate + RMSNorm -> bf16 ==================================
__global__ void __launch_bounds__(256)
post_kernel(const float* __restrict__ ys, const float* __restrict__ convout,
            const float* __restrict__ zx, const float* __restrict__ Dp,
            const float* __restrict__ nw, __nv_bfloat16* __restrict__ yn)
{
    int row = blockIdx.x;
    int tid = threadIdx.x;
    __shared__ float wsum[8];

    float vals[8];
    float ss = 0.0f;
#pragma unroll
    for (int i = 0; i < 8; i++) {
        int c = tid + i * 256;
        float xs = convout[(size_t)row * CONVD + c];
        float yv = ys[(size_t)row * DIN + c] + Dp[c >> 6] * xs;
        float z  = zx[(size_t)row * DPAD + c];
        float g  = z / (1.0f + __expf(-z));
        float v  = yv * g;
        vals[i] = v;
        ss += v * v;
    }
#pragma unroll
    for (int o = 16; o > 0; o >>= 1) ss += __shfl_xor_sync(0xffffffffu, ss, o);
    if ((tid & 31) == 0) wsum[tid >> 5] = ss;
    __syncthreads();
    float tot = 0.0f;
#pragma unroll
    for (int w = 0; w < 8; w++) tot += wsum[w];
    float scale = rsqrtf(tot * (1.0f / DIN) + 1e-5f);
#pragma unroll
    for (int i = 0; i < 8; i++) {
        int c = tid + i * 256;
        yn[(size_t)row * DIN + c] = __float2bfloat16(vals[i] * scale * nw[c]);
    }
}

// ===========================================================================
extern "C" void kernel_launch(void* const* d_in, const int* in_sizes, int n_in,
                              void* d_out, int out_size)
{
    const float* x       = (const float*)d_in[0];
    const float* W_in    = (const float*)d_in[1];
    const float* conv_w  = (const float*)d_in[2];
    const float* conv_b  = (const float*)d_in[3];
    const float* dt_bias = (const float*)d_in[4];
    const float* A_log   = (const float*)d_in[5];
    const float* D_param = (const float*)d_in[6];
    const float* norm_w  = (const float*)d_in[7];
    const float* W_out   = (const float*)d_in[8];
    const float* lscale  = (const float*)d_in[9];
    float* out = (float*)d_out;

    float *zx, *conv, *dt, *dA, *ys, *S, *Hs, *P;
    __nv_bfloat16 *xb, *wib, *wob, *ynb;
    cudaGetSymbolAddress((void**)&zx,   g_zx);
    cudaGetSymbolAddress((void**)&conv, g_conv);
    cudaGetSymbolAddress((void**)&dt,   g_dt);
    cudaGetSymbolAddress((void**)&dA,   g_dA);
    cudaGetSymbolAddress((void**)&ys,   g_ys);
    cudaGetSymbolAddress((void**)&S,    g_S);
    cudaGetSymbolAddress((void**)&Hs,   g_Hs);
    cudaGetSymbolAddress((void**)&P,    g_P);
    cudaGetSymbolAddress((void**)&xb,   g_xb);
    cudaGetSymbolAddress((void**)&wib,  g_wib);
    cudaGetSymbolAddress((void**)&wob,  g_wob);
    cudaGetSymbolAddress((void**)&ynb,  g_ynb);

    cudaFuncSetAttribute(gemm_bf16, cudaFuncAttributeMaxDynamicSharedMemorySize,
                         SMEM_GEMM);

    // 0) converters
    cvt_plain<<<(ROWS * DM + 255) / 256, 256>>>(x, xb, ROWS * DM);
    cvt_pad  <<<(DM * DPAD + 255) / 256, 256>>>(W_in, wib);
    cvt_plain<<<(DIN * DM + 255) / 256, 256>>>(W_out, wob, DIN * DM);

    // 1) in-proj GEMM: [8192,1024] @ [1024,4352] -> zx [8192,4352]
    gemm_bf16<<<dim3(DPAD / 128, ROWS / 128), 128, SMEM_GEMM>>>(
        xb, wib, zx, DM, DM, DPAD, DPAD, nullptr, nullptr);
    // 2) dt softplus + dA
    dt_kernel<<<(ROWS * NH + 255) / 256, 256>>>(zx, dt_bias, A_log, dt, dA);
    // 3) conv1d + silu
    conv_kernel<<<((ROWS / 4) * CONVD + 255) / 256, 256>>>(zx, conv_w, conv_b, conv);
    // 4) chunked SSM scan
    scanA<<<BATCH * NH * NCH, 64>>>(conv, dt, dA, S, P);
    scanB<<<BATCH * NH, 256>>>(S, P, Hs);
    scanC<<<BATCH * NH * NCH, 64>>>(conv, dt, dA, Hs, ys);
    // 5) gate + RMSNorm -> bf16
    post_kernel<<<ROWS, 256>>>(ys, conv, zx, D_param, norm_w, ynb);
    // 6) out-proj GEMM fused with residual+layer_scale -> out
    gemm_bf16<<<dim3(DM / 128, ROWS / 128), 128, SMEM_GEMM>>>(
        ynb, wob, out, DIN, DIN, DM, DM, x, lscale);
}

// round 10
// speedup vs baseline: 4.3288x; 1.0589x over previous
#include <cuda_runtime.h>
#include <cuda_bf16.h>
#include <mma.h>
#include <cstdint>

using namespace nvcuda;

#define ROWS   8192     // BATCH*SEQLEN
#define BATCH  4
#define SEQ    2048
#define DM     1024     // d_model
#define DIN    2048     // d_inner
#define NH     32       // nheads
#define HD     64       // headdim
#define DS     16       // d_state
#define CONVD  2080     // conv dim
#define DPROJ  4160     // in-proj width
#define DPAD   4352     // padded (mult of 128)
#define CL     128      // scan chunk length
#define NCH    16       // chunks per sequence

// ---------------- scratch (static device globals; no runtime alloc) -------
__device__ float          g_zx  [(size_t)ROWS * DPAD];
__device__ float          g_conv[(size_t)ROWS * CONVD];
__device__ float          g_dt  [(size_t)ROWS * NH];
__device__ float          g_dA  [(size_t)ROWS * NH];
__device__ float          g_ys  [(size_t)ROWS * DIN];
__device__ __nv_bfloat16  g_xb  [(size_t)ROWS * DM];
__device__ __nv_bfloat16  g_wib [(size_t)DM * DPAD];   // W_in bf16 [k][n], zero-padded
__device__ __nv_bfloat16  g_wob [(size_t)DIN * DM];    // W_out bf16 [k][n]
__device__ __nv_bfloat16  g_ynb [(size_t)ROWS * DIN];
__device__ float          g_S   [(size_t)BATCH*NH*NCH*HD*DS];
__device__ float          g_Hs  [(size_t)BATCH*NH*NCH*HD*DS];
__device__ float          g_P   [(size_t)BATCH*NH*NCH];

// ================= helpers =================================================
__device__ __forceinline__ void cp16(void* smem, const void* g) {
    unsigned s = (unsigned)__cvta_generic_to_shared(smem);
    asm volatile("cp.async.ca.shared.global [%0], [%1], 16;\n" :: "r"(s), "l"(g));
}
#define CP_COMMIT() asm volatile("cp.async.commit_group;\n" ::: "memory")
#define CP_WAIT(n)  asm volatile("cp.async.wait_group %0;\n" :: "n"(n) : "memory")

// ================= bf16 3-stage GEMM: C[M,N]=A[M,K]@B[K,N] =================
// A row-major [m][k], B row-major [k][n]. CTA 128x128, 128 threads (4 warps),
// warp tile 64x64 (2m x 2n). k-tile 32, 3-stage ring, one sync per k-tile.
// Optional fused epilogue: out = xres + acc*ls (per-column ls).
#define AROW  40                         // A smem row stride (halves)
#define BROW  136                        // B smem row stride (halves)
#define A_H   (128 * AROW)               // 5120 halves
#define B_H   (32 * BROW)                // 4352 halves
#define STG_H (A_H + B_H)                // 9472 halves
#define SMEM_GEMM (3 * STG_H * 2)        // 56832 bytes

__global__ void __launch_bounds__(128, 2)
gemm_bf16(const __nv_bfloat16* __restrict__ A, const __nv_bfloat16* __restrict__ B,
          float* __restrict__ C, int K, int lda, int ldb, int ldc,
          const float* __restrict__ xres, const float* __restrict__ ls)
{
    extern __shared__ __nv_bfloat16 sm[];
    const int tid = threadIdx.x;
    const int wid = tid >> 5;
    const int lid = tid & 31;
    const int wm  = wid >> 1;        // 0..1
    const int wn  = wid & 1;         // 0..1
    const int m0  = blockIdx.y << 7;
    const int n0  = blockIdx.x << 7;

    wmma::fragment<wmma::accumulator, 16, 16, 16, float> acc[4][4];
#pragma unroll
    for (int i = 0; i < 4; i++)
#pragma unroll
        for (int j = 0; j < 4; j++) wmma::fill_fragment(acc[i][j], 0.0f);

    // Each cp16 moves 16 BYTES = 8 halves.
    // A tile: 128 rows x 32 halves = 512 segs; B tile: 32 x 128 = 512 segs.
#define LOAD_TILE(buf, k0)                                                       \
    {                                                                            \
        __nv_bfloat16* sA = sm + (buf) * STG_H;                                  \
        __nv_bfloat16* sB = sA + A_H;                                            \
        _Pragma("unroll")                                                        \
        for (int it = 0; it < 4; ++it) {                                         \
            int idx = tid + it * 128;                                            \
            int r   = idx >> 2;                                                  \
            int c   = (idx & 3) << 3;                                            \
            cp16(sA + r * AROW + c, A + (size_t)(m0 + r) * lda + (k0) + c);      \
        }                                                                        \
        _Pragma("unroll")                                                        \
        for (int it = 0; it < 4; ++it) {                                         \
            int idx = tid + it * 128;                                            \
            int r   = idx >> 4;                                                  \
            int c   = (idx & 15) << 3;                                           \
            cp16(sB + r * BROW + c, B + (size_t)((k0) + r) * ldb + n0 + c);      \
        }                                                                        \
        CP_COMMIT();                                                             \
    }

    const int KT = K >> 5;
    LOAD_TILE(0, 0);
    LOAD_TILE(1, 32);

    int buf = 0;
    for (int kt = 0; kt < KT; kt++) {
        if (kt + 2 < KT) CP_WAIT(1); else CP_WAIT(0);
        __syncthreads();                     // tile kt ready; compute(kt-1) done
        if (kt + 2 < KT) {
            int nbuf = buf + 2; if (nbuf >= 3) nbuf -= 3;   // (buf+2) mod 3
            LOAD_TILE(nbuf, (kt + 2) << 5);
        }

        const __nv_bfloat16* sA = sm + buf * STG_H + (wm * 64) * AROW;
        const __nv_bfloat16* sB = sm + buf * STG_H + A_H + wn * 64;
#pragma unroll
        for (int kk = 0; kk < 32; kk += 16) {
            wmma::fragment<wmma::matrix_a, 16, 16, 16, __nv_bfloat16,
                           wmma::row_major> af[4];
#pragma unroll
            for (int i = 0; i < 4; i++)
                wmma::load_matrix_sync(af[i], sA + (i * 16) * AROW + kk, AROW);
#pragma unroll
            for (int j = 0; j < 4; j++) {
                wmma::fragment<wmma::matrix_b, 16, 16, 16, __nv_bfloat16,
                               wmma::row_major> bf;
                wmma::load_matrix_sync(bf, sB + kk * BROW + j * 16, BROW);
#pragma unroll
                for (int i = 0; i < 4; i++)
                    wmma::mma_sync(acc[i][j], af[i], bf, acc[i][j]);
            }
        }
        buf = (buf == 2) ? 0 : buf + 1;
    }
#undef LOAD_TILE

    if (xres == nullptr) {
#pragma unroll
        for (int i = 0; i < 4; i++)
#pragma unroll
            for (int j = 0; j < 4; j++) {
                int r = m0 + wm * 64 + i * 16;
                int c = n0 + wn * 64 + j * 16;
                wmma::store_matrix_sync(C + (size_t)r * ldc + c, acc[i][j], ldc,
                                        wmma::mem_row_major);
            }
    } else {
        // fused: out = xres + acc * ls, via per-warp smem round-trip
        __syncthreads();
        float* scr = reinterpret_cast<float*>(sm) + wid * 256;
        const int rr = lid >> 1;            // 0..15
        const int cc = (lid & 1) << 3;      // 0 or 8
#pragma unroll
        for (int i = 0; i < 4; i++)
#pragma unroll
            for (int j = 0; j < 4; j++) {
                wmma::store_matrix_sync(scr, acc[i][j], 16, wmma::mem_row_major);
                __syncwarp();
                int r = m0 + wm * 64 + i * 16 + rr;
                int c = n0 + wn * 64 + j * 16 + cc;
                const float* xs = xres + (size_t)r * ldc + c;
                const float* sv = scr + rr * 16 + cc;
                float4 o0, o1;
                o0.x = xs[0] + sv[0] * ls[c + 0];
                o0.y = xs[1] + sv[1] * ls[c + 1];
                o0.z = xs[2] + sv[2] * ls[c + 2];
                o0.w = xs[3] + sv[3] * ls[c + 3];
                o1.x = xs[4] + sv[4] * ls[c + 4];
                o1.y = xs[5] + sv[5] * ls[c + 5];
                o1.z = xs[6] + sv[6] * ls[c + 6];
                o1.w = xs[7] + sv[7] * ls[c + 7];
                float* dst = C + (size_t)r * ldc + c;
                *reinterpret_cast<float4*>(dst)     = o0;
                *reinterpret_cast<float4*>(dst + 4) = o1;
                __syncwarp();
            }
    }
}

// ================= converters ==============================================
__global__ void cvt_plain(const float* __restrict__ src, __nv_bfloat16* __restrict__ dst, int n)
{
    int i = blockIdx.x * blockDim.x + threadIdx.x;
    if (i < n) dst[i] = __float2bfloat16(src[i]);
}
// W_in [DM][DPROJ] -> [DM][DPAD] with zero pad
__global__ void cvt_pad(const float* __restrict__ src, __nv_bfloat16* __restrict__ dst)
{
    int i = blockIdx.x * blockDim.x + threadIdx.x;
    if (i >= DM * DPAD) return;
    int r = i / DPAD, c = i - r * DPAD;
    dst[i] = __float2bfloat16(c < DPROJ ? src[(size_t)r * DPROJ + c] : 0.0f);
}

// ================= dt / dA ==================================================
__global__ void dt_kernel(const float* __restrict__ zx,
                          const float* __restrict__ dt_bias,
                          const float* __restrict__ A_log,
                          float* __restrict__ dt, float* __restrict__ dA)
{
    int idx = blockIdx.x * blockDim.x + threadIdx.x;
    if (idx >= ROWS * NH) return;
    int row = idx >> 5, h = idx & 31;
    float v = zx[(size_t)row * DPAD + DIN + CONVD + h] + dt_bias[h];
    float d = (v > 20.0f) ? v : log1pf(__expf(v));
    dt[idx] = d;
    dA[idx] = __expf(d * (-__expf(A_log[h])));
}

// ================= causal depthwise conv1d + silu (sliding window) =========
__global__ void conv_kernel(const float* __restrict__ zx,
                            const float* __restrict__ cw,
                            const float* __restrict__ cb,
                            float* __restrict__ convout)
{
    int idx = blockIdx.x * blockDim.x + threadIdx.x;
    if (idx >= (ROWS / 4) * CONVD) return;
    int rowq = idx / CONVD;
    int c    = idx - rowq * CONVD;
    int b    = rowq >> 9;
    int lq   = (rowq & 511) << 2;

    float w0 = cw[c * 4 + 0], w1 = cw[c * 4 + 1];
    float w2 = cw[c * 4 + 2], w3 = cw[c * 4 + 3];
    float bias = cb[c];

    float v[7];
#pragma unroll
    for (int j = 0; j < 7; j++) {
        int lt = lq + j - 3;
        v[j] = (lt >= 0) ? zx[(size_t)(b * SEQ + lt) * DPAD + DIN + c] : 0.0f;
    }
#pragma unroll
    for (int t = 0; t < 4; t++) {
        float acc = bias + v[t] * w0 + v[t + 1] * w1 + v[t + 2] * w2 + v[t + 3] * w3;
        convout[(size_t)(b * SEQ + lq + t) * CONVD + c] = acc / (1.0f + __expf(-acc));
    }
}

// ================= chunked SSM scan ========================================
__global__ void __launch_bounds__(64)
scanA(const float* __restrict__ convout, const float* __restrict__ dt,
      const float* __restrict__ dA, float* __restrict__ S, float* __restrict__ P)
{
    int blk = blockIdx.x;
    int bh  = blk >> 4, ch = blk & 15;
    int b   = bh >> 5,  h  = bh & 31;
    int p   = threadIdx.x;
    const size_t rowbase = (size_t)b * SEQ + ch * CL;

    float hst[DS];
#pragma unroll
    for (int n = 0; n < DS; n++) hst[n] = 0.0f;
    float pacc = 1.0f;

    __shared__ __align__(16) float sB[32][DS];
    __shared__ float sdt[32], sdA[32];

    for (int t0 = 0; t0 < CL; t0 += 32) {
        for (int i = p; i < 32 * DS; i += 64) {
            int tt = i >> 4, n = i & 15;
            sB[tt][n] = convout[(rowbase + t0 + tt) * CONVD + DIN + n];
        }
        for (int i = p; i < 32; i += 64) {
            sdt[i] = dt[(rowbase + t0 + i) * NH + h];
            sdA[i] = dA[(rowbase + t0 + i) * NH + h];
        }
        float rx[32];
#pragma unroll
        for (int tt = 0; tt < 32; tt++)
            rx[tt] = convout[(rowbase + t0 + tt) * CONVD + h * HD + p];
        __syncthreads();
#pragma unroll
        for (int tt = 0; tt < 32; tt++) {
            float dAv = sdA[tt];
            float dtx = sdt[tt] * rx[tt];
            pacc *= dAv;
            const float4* Bp = reinterpret_cast<const float4*>(sB[tt]);
#pragma unroll
            for (int q = 0; q < 4; q++) {
                float4 Bv = Bp[q];
                hst[q*4+0] = fmaf(hst[q*4+0], dAv, dtx * Bv.x);
                hst[q*4+1] = fmaf(hst[q*4+1], dAv, dtx * Bv.y);
                hst[q*4+2] = fmaf(hst[q*4+2], dAv, dtx * Bv.z);
                hst[q*4+3] = fmaf(hst[q*4+3], dAv, dtx * Bv.w);
            }
        }
        __syncthreads();
    }
    float4* Sp = reinterpret_cast<float4*>(S + (size_t)blk * (HD * DS) + p * DS);
#pragma unroll
    for (int q = 0; q < 4; q++)
        Sp[q] = make_float4(hst[q*4+0], hst[q*4+1], hst[q*4+2], hst[q*4+3]);
    if (p == 0) P[blk] = pacc;
}

__global__ void __launch_bounds__(256)
scanB(const float* __restrict__ S, const float* __restrict__ P,
      float* __restrict__ Hs)
{
    int bh  = blockIdx.x;
    int tid = threadIdx.x;
    float4 H = make_float4(0.f, 0.f, 0.f, 0.f);
    for (int c = 0; c < NCH; c++) {
        size_t off = ((size_t)bh * NCH + c) * (HD * DS) + tid * 4;
        *reinterpret_cast<float4*>(Hs + off) = H;
        float4 sv = *reinterpret_cast<const float4*>(S + off);
        float pc = P[bh * NCH + c];
        H.x = H.x * pc + sv.x;
        H.y = H.y * pc + sv.y;
        H.z = H.z * pc + sv.z;
        H.w = H.w * pc + sv.w;
    }
}

__global__ void __launch_bounds__(64)
scanC(const float* __restrict__ convout, const float* __restrict__ dt,
      const float* __restrict__ dA, const float* __restrict__ Hs,
      float* __restrict__ ys)
{
    int blk = blockIdx.x;
    int bh  = blk >> 4, ch = blk & 15;
    int b   = bh >> 5,  h  = bh & 31;
    int p   = threadIdx.x;
    const size_t rowbase = (size_t)b * SEQ + ch * CL;

    float hst[DS];
    {
        const float4* Hp = reinterpret_cast<const float4*>(
            Hs + (size_t)blk * (HD * DS) + p * DS);
#pragma unroll
        for (int q = 0; q < 4; q++) {
            float4 v = Hp[q];
            hst[q*4+0] = v.x; hst[q*4+1] = v.y; hst[q*4+2] = v.z; hst[q*4+3] = v.w;
        }
    }

    __shared__ __align__(16) float sB[32][DS];
    __shared__ __align__(16) float sC[32][DS];
    __shared__ float sdt[32], sdA[32];

    for (int t0 = 0; t0 < CL; t0 += 32) {
        for (int i = p; i < 32 * DS; i += 64) {
            int tt = i >> 4, n = i & 15;
            size_t r = (rowbase + t0 + tt) * CONVD;
            sB[tt][n] = convout[r + DIN + n];
            sC[tt][n] = convout[r + DIN + DS + n];
        }
        for (int i = p; i < 32; i += 64) {
            sdt[i] = dt[(rowbase + t0 + i) * NH + h];
            sdA[i] = dA[(rowbase + t0 + i) * NH + h];
        }
        float rx[32];
#pragma unroll
        for (int tt = 0; tt < 32; tt++)
            rx[tt] = convout[(rowbase + t0 + tt) * CONVD + h * HD + p];
        __syncthreads();
#pragma unroll
        for (int tt = 0; tt < 32; tt++) {
            float dAv = sdA[tt];
            float dtx = sdt[tt] * rx[tt];
            const float4* Bp = reinterpret_cast<const float4*>(sB[tt]);
            const float4* Cp = reinterpret_cast<const float4*>(sC[tt]);
            float yp0 = 0.f, yp1 = 0.f, yp2 = 0.f, yp3 = 0.f;
#pragma unroll
            for (int q = 0; q < 4; q++) {
                float4 Bv = Bp[q];
                float4 Cv = Cp[q];
                hst[q*4+0] = fmaf(hst[q*4+0], dAv, dtx * Bv.x); yp0 += hst[q*4+0] * Cv.x;
                hst[q*4+1] = fmaf(hst[q*4+1], dAv, dtx * Bv.y); yp1 += hst[q*4+1] * Cv.y;
                hst[q*4+2] = fmaf(hst[q*4+2], dAv, dtx * Bv.z); yp2 += hst[q*4+2] * Cv.z;
                hst[q*4+3] = fmaf(hst[q*4+3], dAv, dtx * Bv.w); yp3 += hst[q*4+3] * Cv.w;
            }
            ys[(rowbase + t0 + tt) * DIN + h * HD + p] = (yp0 + yp1) + (yp2 + yp3);
        }
        __syncthreads();
    }
}

// ================= gate + RMSNorm -> bf16 ==================================
__global__ void __launch_bounds__(256)
post_kernel(const float* __restrict__ ys, const float* __restrict__ convout,
            const float* __restrict__ zx, const float* __restrict__ Dp,
            const float* __restrict__ nw, __nv_bfloat16* __restrict__ yn)
{
    int row = blockIdx.x;
    int tid = threadIdx.x;
    __shared__ float wsum[8];

    float vals[8];
    float ss = 0.0f;
#pragma unroll
    for (int i = 0; i < 8; i++) {
        int c = tid + i * 256;
        float xs = convout[(size_t)row * CONVD + c];
        float yv = ys[(size_t)row * DIN + c] + Dp[c >> 6] * xs;
        float z  = zx[(size_t)row * DPAD + c];
        float g  = z / (1.0f + __expf(-z));
        float v  = yv * g;
        vals[i] = v;
        ss += v * v;
    }
#pragma unroll
    for (int o = 16; o > 0; o >>= 1) ss += __shfl_xor_sync(0xffffffffu, ss, o);
    if ((tid & 31) == 0) wsum[tid >> 5] = ss;
    __syncthreads();
    float tot = 0.0f;
#pragma unroll
    for (int w = 0; w < 8; w++) tot += wsum[w];
    float scale = rsqrtf(tot * (1.0f / DIN) + 1e-5f);
#pragma unroll
    for (int i = 0; i < 8; i++) {
        int c = tid + i * 256;
        yn[(size_t)row * DIN + c] = __float2bfloat16(vals[i] * scale * nw[c]);
    }
}

// ===========================================================================
extern "C" void kernel_launch(void* const* d_in, const int* in_sizes, int n_in,
                              void* d_out, int out_size)
{
    const float* x       = (const float*)d_in[0];
    const float* W_in    = (const float*)d_in[1];
    const float* conv_w  = (const float*)d_in[2];
    const float* conv_b  = (const float*)d_in[3];
    const float* dt_bias = (const float*)d_in[4];
    const float* A_log   = (const float*)d_in[5];
    const float* D_param = (const float*)d_in[6];
    const float* norm_w  = (const float*)d_in[7];
    const float* W_out   = (const float*)d_in[8];
    const float* lscale  = (const float*)d_in[9];
    float* out = (float*)d_out;

    float *zx, *conv, *dt, *dA, *ys, *S, *Hs, *P;
    __nv_bfloat16 *xb, *wib, *wob, *ynb;
    cudaGetSymbolAddress((void**)&zx,   g_zx);
    cudaGetSymbolAddress((void**)&conv, g_conv);
    cudaGetSymbolAddress((void**)&dt,   g_dt);
    cudaGetSymbolAddress((void**)&dA,   g_dA);
    cudaGetSymbolAddress((void**)&ys,   g_ys);
    cudaGetSymbolAddress((void**)&S,    g_S);
    cudaGetSymbolAddress((void**)&Hs,   g_Hs);
    cudaGetSymbolAddress((void**)&P,    g_P);
    cudaGetSymbolAddress((void**)&xb,   g_xb);
    cudaGetSymbolAddress((void**)&wib,  g_wib);
    cudaGetSymbolAddress((void**)&wob,  g_wob);
    cudaGetSymbolAddress((void**)&ynb,  g_ynb);

    cudaFuncSetAttribute(gemm_bf16, cudaFuncAttributeMaxDynamicSharedMemorySize,
                         SMEM_GEMM);

    // 0) converters
    cvt_plain<<<(ROWS * DM + 255) / 256, 256>>>(x, xb, ROWS * DM);
    cvt_pad  <<<(DM * DPAD + 255) / 256, 256>>>(W_in, wib);
    cvt_plain<<<(DIN * DM + 255) / 256, 256>>>(W_out, wob, DIN * DM);

    // 1) in-proj GEMM: [8192,1024] @ [1024,4352] -> zx [8192,4352]
    gemm_bf16<<<dim3(DPAD / 128, ROWS / 128), 128, SMEM_GEMM>>>(
        xb, wib, zx, DM, DM, DPAD, DPAD, nullptr, nullptr);
    // 2) dt softplus + dA
    dt_kernel<<<(ROWS * NH + 255) / 256, 256>>>(zx, dt_bias, A_log, dt, dA);
    // 3) conv1d + silu
    conv_kernel<<<((ROWS / 4) * CONVD + 255) / 256, 256>>>(zx, conv_w, conv_b, conv);
    // 4) chunked SSM scan
    scanA<<<BATCH * NH * NCH, 64>>>(conv, dt, dA, S, P);
    scanB<<<BATCH * NH, 256>>>(S, P, Hs);
    scanC<<<BATCH * NH * NCH, 64>>>(conv, dt, dA, Hs, ys);
    // 5) gate + RMSNorm -> bf16
    post_kernel<<<ROWS, 256>>>(ys, conv, zx, D_param, norm_w, ynb);
    // 6) out-proj GEMM fused with residual+layer_scale -> out
    gemm_bf16<<<dim3(DM / 128, ROWS / 128), 128, SMEM_GEMM>>>(
        ynb, wob, out, DIN, DIN, DM, DM, x, lscale);
}